// round 8
// baseline (speedup 1.0000x reference)
#include <cuda_runtime.h>
#include <cuda_bf16.h>
#include <math.h>
#include <stdint.h>

#define BBATCH 8
#define SEQ    2048
#define DMODEL 768
#define NHEAD  12
#define HD     64
#define MR     (BBATCH*SEQ)      // 16384
#define NQ     (3*DMODEL)        // 2304

typedef __nv_bfloat16 bf16;

// ---- static device scratch (no allocations allowed) ----
__device__ bf16  g_xh[(size_t)MR*DMODEL],  g_xl[(size_t)MR*DMODEL];
__device__ bf16  g_Wth[(size_t)NQ*DMODEL], g_Wtl[(size_t)NQ*DMODEL];   // [n][k] n-major
__device__ float g_bqkv[NQ];
__device__ bf16  g_Wpth[(size_t)DMODEL*DMODEL], g_Wptl[(size_t)DMODEL*DMODEL]; // [n][k]
__device__ bf16  g_qh[(size_t)MR*NQ],      g_ql[(size_t)MR*NQ];        // QKV split
__device__ bf16  g_ch[(size_t)MR*DMODEL],  g_cl[(size_t)MR*DMODEL];    // ctx split

__device__ __forceinline__ void splitf(float v, bf16 &h, bf16 &l){
    h = __float2bfloat16(v);
    l = __float2bfloat16(v - __bfloat162float(h));
}
__device__ __forceinline__ uint32_t pack2(bf16 a, bf16 b){
    union { bf16 v[2]; uint32_t u; } t; t.v[0]=a; t.v[1]=b; return t.u;
}
// Truncation split of two fp32 probs into packed bf16x2 hi + bf16x2 lo (exact 2-term).
__device__ __forceinline__ void splitp2(float p0, float p1, uint32_t &hi, uint32_t &lo){
    uint32_t u0 = __float_as_uint(p0), u1 = __float_as_uint(p1);
    hi = (u0 >> 16) | (u1 & 0xFFFF0000u);
    float r0 = p0 - __uint_as_float(u0 & 0xFFFF0000u);
    float r1 = p1 - __uint_as_float(u1 & 0xFFFF0000u);
    asm("cvt.rn.bf16x2.f32 %0, %1, %2;" : "=r"(lo) : "f"(r1), "f"(r0));
}
__device__ __forceinline__ void mma16816(float c[4], const uint32_t a[4],
                                         uint32_t b0, uint32_t b1){
    asm volatile("mma.sync.aligned.m16n8k16.row.col.f32.bf16.bf16.f32 "
        "{%0,%1,%2,%3},{%4,%5,%6,%7},{%8,%9},{%0,%1,%2,%3};"
        : "+f"(c[0]),"+f"(c[1]),"+f"(c[2]),"+f"(c[3])
        : "r"(a[0]),"r"(a[1]),"r"(a[2]),"r"(a[3]),"r"(b0),"r"(b1));
}
__device__ __forceinline__ uint32_t smem_u32(const void* p){
    uint32_t r;
    asm("{ .reg .u64 t; cvta.to.shared.u64 t, %1; cvt.u32.u64 %0, t; }" : "=r"(r) : "l"(p));
    return r;
}
__device__ __forceinline__ void cp16(uint32_t dst, const void* src){
    asm volatile("cp.async.cg.shared.global [%0], [%1], 16;" :: "r"(dst), "l"(src));
}
#define CP_COMMIT()  asm volatile("cp.async.commit_group;" ::: "memory")
#define CP_WAIT(n)   asm volatile("cp.async.wait_group %0;" :: "n"(n) : "memory")
#define LDSM4(r0,r1,r2,r3,a) \
    asm volatile("ldmatrix.sync.aligned.m8n8.x4.shared.b16 {%0,%1,%2,%3}, [%4];" \
        : "=r"(r0),"=r"(r1),"=r"(r2),"=r"(r3) : "r"(a))
#define LDSM4T(r0,r1,r2,r3,a) \
    asm volatile("ldmatrix.sync.aligned.m8n8.x4.trans.shared.b16 {%0,%1,%2,%3}, [%4];" \
        : "=r"(r0),"=r"(r1),"=r"(r2),"=r"(r3) : "r"(a))

// Fold attention score scale AND log2(e) into Wq/bq so softmax is exp2(s - m).
#define QFOLD (1.4426950408889634f / (8.0f + 1e-6f))

// ============================================================================
// Prep kernels
// ============================================================================
__global__ void split_x_kernel(const float* __restrict__ x){
    size_t i = (size_t)blockIdx.x*blockDim.x + threadIdx.x;
    if (i < (size_t)MR*DMODEL) splitf(x[i], g_xh[i], g_xl[i]);
}

__global__ void prep_all_kernel(const float* __restrict__ Wq, const float* __restrict__ Wk,
                                const float* __restrict__ Wv, const float* __restrict__ bq,
                                const float* __restrict__ bk, const float* __restrict__ bv,
                                const float* __restrict__ Wp){
    int idx = blockIdx.x*blockDim.x + threadIdx.x;
    if (idx < NQ*DMODEL){
        int n = idx / DMODEL, k = idx - n*DMODEL;
        int sec = n / DMODEL;
        int r = n - sec*DMODEL;
        int h = r >> 6, e = r & 63;
        const float* W = (sec==0) ? Wq : (sec==1 ? Wk : Wv);
        float v = W[((size_t)h*DMODEL + k)*HD + e];
        if (sec == 0) v *= QFOLD;
        splitf(v, g_Wth[idx], g_Wtl[idx]);
    }
    if (idx < DMODEL*DMODEL){
        int n = idx / DMODEL, k = idx - n*DMODEL;
        splitf(Wp[(size_t)k*DMODEL + n], g_Wpth[idx], g_Wptl[idx]);
    }
    if (idx < NQ){
        int sec = idx / DMODEL, r = idx - sec*DMODEL;
        const float* bb = (sec==0) ? bq : (sec==1 ? bk : bv);
        float v = bb[r];
        if (sec == 0) v *= QFOLD;
        g_bqkv[idx] = v;
    }
}

// ============================================================================
// Split-bf16 MMA GEMM, cp.async double-buffered, ldmatrix fragment loads.
// 128x128 tile, BK=32, 256 threads (8 warps, 2m x 4n), warp tile 64x32.
// ============================================================================
#define GSA   40
#define GARR  (128*GSA)          // elems per array
#define GSTG  (4*GARR)           // Ah,Al,Bh,Bl per stage
#define GSMEM (2*GSTG*2)         // bytes: 2 stages  = 81920

template<bool SPLIT_OUT>
__device__ __forceinline__ void gemm_core(
    const bf16* __restrict__ Ah_, const bf16* __restrict__ Al_,
    const bf16* __restrict__ Bth_, const bf16* __restrict__ Btl_,
    const float* __restrict__ bias, int K, int N,
    bf16* __restrict__ Ch, bf16* __restrict__ Cl, float* __restrict__ Cf)
{
    extern __shared__ __align__(16) bf16 gsm[];
    const uint32_t aS = smem_u32(gsm);
    const int tid  = threadIdx.x;
    const int lane = tid & 31, wid = tid >> 5;
    const int g = lane >> 2, t = lane & 3;
    const int wm = (wid & 1) * 64, wn = (wid >> 1) * 32;
    const size_t bm0 = (size_t)blockIdx.y * 128;
    const size_t bn0 = (size_t)blockIdx.x * 128;

    const int offA = (lane & 15)*GSA + (lane >> 4)*8;
    const int offB = ((lane & 7) + (lane >> 4)*8)*GSA + ((lane >> 3) & 1)*8;

    const bf16* srcs[4] = { Ah_ + bm0*K, Al_ + bm0*K, Bth_ + bn0*K, Btl_ + bn0*K };

    auto issue = [&](int it, int stg){
        uint32_t base = aS + stg*GSTG*2;
        #pragma unroll
        for (int arr=0; arr<4; arr++){
            const bf16* src = srcs[arr];
            #pragma unroll
            for (int j=0;j<2;j++){
                int cc = tid + j*256;            // 0..511
                int r = cc >> 2, col = (cc & 3) << 3;
                cp16(base + 2*(arr*GARR + r*GSA + col), src + (size_t)r*K + it*32 + col);
            }
        }
        CP_COMMIT();
    };

    float acc[4][4][4];
    #pragma unroll
    for (int a=0;a<4;a++)
        #pragma unroll
        for (int b=0;b<4;b++)
            #pragma unroll
            for (int c=0;c<4;c++) acc[a][b][c] = 0.0f;

    const int NIT = K/32;
    issue(0, 0);

    for (int it = 0; it < NIT; it++){
        const int stg = it & 1;
        CP_WAIT(0);
        __syncthreads();
        if (it + 1 < NIT) issue(it + 1, stg ^ 1);

        const uint32_t aAh = aS + stg*GSTG*2;
        const uint32_t aAl = aAh + GARR*2;
        const uint32_t aBh = aAl + GARR*2;
        const uint32_t aBl = aBh + GARR*2;

        #pragma unroll
        for (int ks = 0; ks < 32; ks += 16){
            uint32_t afh[4][4], afl[4][4];
            #pragma unroll
            for (int mt=0; mt<4; mt++){
                uint32_t adr = aAh + 2*((wm + mt*16)*GSA + ks + offA);
                LDSM4(afh[mt][0], afh[mt][1], afh[mt][2], afh[mt][3], adr);
                adr = aAl + 2*((wm + mt*16)*GSA + ks + offA);
                LDSM4(afl[mt][0], afl[mt][1], afl[mt][2], afl[mt][3], adr);
            }
            uint32_t bh[2][4], bl[2][4];
            #pragma unroll
            for (int np=0; np<2; np++){
                uint32_t adr = aBh + 2*((wn + np*16)*GSA + ks + offB);
                LDSM4(bh[np][0], bh[np][1], bh[np][2], bh[np][3], adr);
                adr = aBl + 2*((wn + np*16)*GSA + ks + offB);
                LDSM4(bl[np][0], bl[np][1], bl[np][2], bl[np][3], adr);
            }
            #pragma unroll
            for (int np=0; np<2; np++){
                #pragma unroll
                for (int hf=0; hf<2; hf++){
                    int nt = np*2 + hf;
                    uint32_t bh0 = bh[np][2*hf], bh1 = bh[np][2*hf+1];
                    uint32_t bl0 = bl[np][2*hf], bl1 = bl[np][2*hf+1];
                    #pragma unroll
                    for (int mt=0; mt<4; mt++){
                        mma16816(acc[mt][nt], afh[mt], bh0, bh1);
                        mma16816(acc[mt][nt], afh[mt], bl0, bl1);
                        mma16816(acc[mt][nt], afl[mt], bh0, bh1);
                    }
                }
            }
        }
    }

    #pragma unroll
    for (int mt=0; mt<4; mt++){
        #pragma unroll
        for (int nt=0; nt<4; nt++){
            size_t n = bn0 + wn + nt*8 + 2*t;
            float b0v = bias[n], b1v = bias[n+1];
            size_t m = bm0 + wm + mt*16 + g;
            float v00 = acc[mt][nt][0] + b0v, v01 = acc[mt][nt][1] + b1v;
            float v10 = acc[mt][nt][2] + b0v, v11 = acc[mt][nt][3] + b1v;
            if (SPLIT_OUT){
                bf16 h0,l0,h1,l1;
                splitf(v00,h0,l0); splitf(v01,h1,l1);
                *(uint32_t*)&Ch[m*N + n] = pack2(h0,h1);
                *(uint32_t*)&Cl[m*N + n] = pack2(l0,l1);
                splitf(v10,h0,l0); splitf(v11,h1,l1);
                *(uint32_t*)&Ch[(m+8)*N + n] = pack2(h0,h1);
                *(uint32_t*)&Cl[(m+8)*N + n] = pack2(l0,l1);
            } else {
                float2 fa; fa.x = v00; fa.y = v01;
                float2 fb; fb.x = v10; fb.y = v11;
                *(float2*)&Cf[m*N + n]     = fa;
                *(float2*)&Cf[(m+8)*N + n] = fb;
            }
        }
    }
}

__global__ __launch_bounds__(256) void gemm_qkv_kernel(){
    gemm_core<true>(g_xh, g_xl, g_Wth, g_Wtl, g_bqkv, DMODEL, NQ, g_qh, g_ql, nullptr);
}
__global__ __launch_bounds__(256) void gemm_out_kernel(const float* __restrict__ bp,
                                                       float* __restrict__ out){
    gemm_core<false>(g_ch, g_cl, g_Wpth, g_Wptl, bp, DMODEL, DMODEL, nullptr, nullptr, out);
}

// ============================================================================
// Flash attention: 128-q-row blocks, ldmatrix frags, cp.async double-buffered K/V.
// Q pre-scaled by QFOLD (in weights) -> softmax = exp2(s - m), no score scaling.
// ============================================================================
#define KV_ARR   (64*72)
#define KV_ARRB  (KV_ARR*2)
#define KV_BUFB  (4*KV_ARRB)
#define ATTN_SMEM (2*128*72*2 + 2*KV_BUFB)   // 110592

__global__ __launch_bounds__(128) void attn_mma(){
    extern __shared__ __align__(16) char smraw[];
    bf16* Qh = (bf16*)smraw;               // [128][72]
    bf16* Ql = Qh + 128*72;
    const uint32_t aQh = smem_u32(Qh), aQl = smem_u32(Ql);
    const uint32_t aKV = aQh + 2*2*128*72;

    const int tid  = threadIdx.x;
    const int lane = tid & 31, wid = tid >> 5;
    const int g = lane >> 2, t = lane & 3;
    const int b = blockIdx.y / NHEAD, h = blockIdx.y % NHEAD;
    const int q0 = blockIdx.x * 128;
    const size_t rowbase = (size_t)b*SEQ*NQ + (size_t)h*HD;

    #pragma unroll
    for (int i=0;i<8;i++){
        int v = tid + i*128;
        int r = v >> 3, c = (v & 7) << 3;
        *(uint4*)&Qh[r*72 + c] = *(const uint4*)&g_qh[rowbase + (size_t)(q0+r)*NQ + c];
        *(uint4*)&Ql[r*72 + c] = *(const uint4*)&g_ql[rowbase + (size_t)(q0+r)*NQ + c];
    }

    auto issue_kv = [&](int it, int bufIdx){
        uint32_t base = aKV + bufIdx*KV_BUFB;
        #pragma unroll
        for (int i=0;i<4;i++){
            int v = tid + i*128;
            int r = v >> 3, c = (v & 7) << 3;
            size_t grow = rowbase + (size_t)(it*64 + r)*NQ;
            uint32_t doff = 2*(r*72 + c);
            cp16(base + 0*KV_ARRB + doff, &g_qh[grow +   DMODEL + c]);
            cp16(base + 1*KV_ARRB + doff, &g_ql[grow +   DMODEL + c]);
            cp16(base + 2*KV_ARRB + doff, &g_qh[grow + 2*DMODEL + c]);
            cp16(base + 3*KV_ARRB + doff, &g_ql[grow + 2*DMODEL + c]);
        }
        CP_COMMIT();
    };

    const int offA = (lane & 15)*72 + (lane >> 4)*8;
    const int offB = ((lane & 7) + (lane >> 4)*8)*72 + ((lane >> 3) & 1)*8;
    const int offV = ((lane & 7) + ((lane >> 3) & 1)*8)*72 + (lane >> 4)*8;

    float m[2][2], l[2][2], o[2][8][4];
    #pragma unroll
    for (int mt=0;mt<2;mt++){
        m[mt][0]=-1e30f; m[mt][1]=-1e30f; l[mt][0]=0.0f; l[mt][1]=0.0f;
        #pragma unroll
        for (int e=0;e<8;e++){ o[mt][e][0]=0; o[mt][e][1]=0; o[mt][e][2]=0; o[mt][e][3]=0; }
    }
    const int NT = SEQ/64;

    issue_kv(0, 0);

    for (int it = 0; it < NT; it++){
        const int buf = it & 1;
        __syncthreads();
        if (it + 1 < NT){ issue_kv(it + 1, buf ^ 1); CP_WAIT(1); }
        else            { CP_WAIT(0); }
        __syncthreads();

        const uint32_t aKh = aKV + buf*KV_BUFB;
        const uint32_t aKl = aKh + KV_ARRB;
        const uint32_t aVh = aKl + KV_ARRB;
        const uint32_t aVl = aVh + KV_ARRB;

        // ---- S = Q K^T (3-term split), 2 m-tiles per warp ----
        float s[2][8][4];
        #pragma unroll
        for (int mt=0;mt<2;mt++)
            #pragma unroll
            for (int nt=0;nt<8;nt++){ s[mt][nt][0]=0; s[mt][nt][1]=0; s[mt][nt][2]=0; s[mt][nt][3]=0; }

        #pragma unroll
        for (int ks=0; ks<64; ks+=16){
            uint32_t ah[2][4], al[2][4];
            #pragma unroll
            for (int mt=0; mt<2; mt++){
                uint32_t adr = aQh + 2*((wid*32 + mt*16)*72 + ks + offA);
                LDSM4(ah[mt][0], ah[mt][1], ah[mt][2], ah[mt][3], adr);
                adr = aQl + 2*((wid*32 + mt*16)*72 + ks + offA);
                LDSM4(al[mt][0], al[mt][1], al[mt][2], al[mt][3], adr);
            }
            #pragma unroll
            for (int np=0; np<4; np++){
                uint32_t kh0,kh1,kh2,kh3, kl0,kl1,kl2,kl3;
                uint32_t adr = aKh + 2*((np*16)*72 + ks + offB);
                LDSM4(kh0,kh1,kh2,kh3, adr);
                adr = aKl + 2*((np*16)*72 + ks + offB);
                LDSM4(kl0,kl1,kl2,kl3, adr);
                #pragma unroll
                for (int mt=0; mt<2; mt++){
                    mma16816(s[mt][2*np  ], ah[mt], kh0, kh1);
                    mma16816(s[mt][2*np  ], ah[mt], kl0, kl1);
                    mma16816(s[mt][2*np  ], al[mt], kh0, kh1);
                    mma16816(s[mt][2*np+1], ah[mt], kh2, kh3);
                    mma16816(s[mt][2*np+1], ah[mt], kl2, kl3);
                    mma16816(s[mt][2*np+1], al[mt], kh2, kh3);
                }
            }
        }

        // ---- Online softmax per m-tile (base-2 domain, scores pre-scaled) ----
        uint32_t ph01[2][8], ph23[2][8], pl01[2][8], pl23[2][8];
        #pragma unroll
        for (int mt=0; mt<2; mt++){
            float rm0 = -1e30f, rm1 = -1e30f;
            #pragma unroll
            for (int nt=0;nt<8;nt++){
                rm0 = fmaxf(rm0, fmaxf(s[mt][nt][0], s[mt][nt][1]));
                rm1 = fmaxf(rm1, fmaxf(s[mt][nt][2], s[mt][nt][3]));
            }
            rm0 = fmaxf(rm0, __shfl_xor_sync(0xffffffffu, rm0, 1));
            rm0 = fmaxf(rm0, __shfl_xor_sync(0xffffffffu, rm0, 2));
            rm1 = fmaxf(rm1, __shfl_xor_sync(0xffffffffu, rm1, 1));
            rm1 = fmaxf(rm1, __shfl_xor_sync(0xffffffffu, rm1, 2));
            float mn0 = fmaxf(m[mt][0], rm0), mn1 = fmaxf(m[mt][1], rm1);
            float cr0 = exp2f(m[mt][0] - mn0), cr1 = exp2f(m[mt][1] - mn1);
            m[mt][0] = mn0; m[mt][1] = mn1;

            float rs0 = 0.0f, rs1 = 0.0f;
            #pragma unroll
            for (int nt=0;nt<8;nt++){
                float p0 = exp2f(s[mt][nt][0]-mn0), p1 = exp2f(s[mt][nt][1]-mn0);
                float p2 = exp2f(s[mt][nt][2]-mn1), p3 = exp2f(s[mt][nt][3]-mn1);
                rs0 += p0+p1; rs1 += p2+p3;
                splitp2(p0, p1, ph01[mt][nt], pl01[mt][nt]);
                splitp2(p2, p3, ph23[mt][nt], pl23[mt][nt]);
            }
            rs0 += __shfl_xor_sync(0xffffffffu, rs0, 1);
            rs0 += __shfl_xor_sync(0xffffffffu, rs0, 2);
            rs1 += __shfl_xor_sync(0xffffffffu, rs1, 1);
            rs1 += __shfl_xor_sync(0xffffffffu, rs1, 2);
            l[mt][0] = l[mt][0]*cr0 + rs0; l[mt][1] = l[mt][1]*cr1 + rs1;
            #pragma unroll
            for (int e=0;e<8;e++){
                o[mt][e][0]*=cr0; o[mt][e][1]*=cr0; o[mt][e][2]*=cr1; o[mt][e][3]*=cr1;
            }
        }

        // ---- O += P @ V ----
        #pragma unroll
        for (int j2=0; j2<4; j2++){
            uint32_t aP[2][4], aPl[2][4];
            #pragma unroll
            for (int mt=0; mt<2; mt++){
                aP [mt][0]=ph01[mt][2*j2];   aP [mt][1]=ph23[mt][2*j2];
                aP [mt][2]=ph01[mt][2*j2+1]; aP [mt][3]=ph23[mt][2*j2+1];
                aPl[mt][0]=pl01[mt][2*j2];   aPl[mt][1]=pl23[mt][2*j2];
                aPl[mt][2]=pl01[mt][2*j2+1]; aPl[mt][3]=pl23[mt][2*j2+1];
            }
            #pragma unroll
            for (int ep=0; ep<4; ep++){
                uint32_t vh0,vh1,vh2,vh3, vl0,vl1,vl2,vl3;
                uint32_t adr = aVh + 2*((j2*16)*72 + ep*16 + offV);
                LDSM4T(vh0,vh1,vh2,vh3, adr);
                adr = aVl + 2*((j2*16)*72 + ep*16 + offV);
                LDSM4T(vl0,vl1,vl2,vl3, adr);
                #pragma unroll
                for (int mt=0; mt<2; mt++){
                    mma16816(o[mt][2*ep  ], aP[mt],  vh0, vh1);
                    mma16816(o[mt][2*ep  ], aP[mt],  vl0, vl1);
                    mma16816(o[mt][2*ep  ], aPl[mt], vh0, vh1);
                    mma16816(o[mt][2*ep+1], aP[mt],  vh2, vh3);
                    mma16816(o[mt][2*ep+1], aP[mt],  vl2, vl3);
                    mma16816(o[mt][2*ep+1], aPl[mt], vh2, vh3);
                }
            }
        }
    }

    // ---- Normalize, split, write ctx hi/lo ----
    #pragma unroll
    for (int mt=0; mt<2; mt++){
        float i0 = 1.0f/l[mt][0], i1 = 1.0f/l[mt][1];
        size_t row = (size_t)b*SEQ + q0 + wid*32 + mt*16 + g;
        #pragma unroll
        for (int et=0; et<8; et++){
            int n = h*HD + et*8 + 2*t;
            float v00 = o[mt][et][0]*i0, v01 = o[mt][et][1]*i0;
            float v10 = o[mt][et][2]*i1, v11 = o[mt][et][3]*i1;
            bf16 a,bb,c,d;
            splitf(v00,a,bb); splitf(v01,c,d);
            *(uint32_t*)&g_ch[row*DMODEL + n] = pack2(a,c);
            *(uint32_t*)&g_cl[row*DMODEL + n] = pack2(bb,d);
            splitf(v10,a,bb); splitf(v11,c,d);
            *(uint32_t*)&g_ch[(row+8)*DMODEL + n] = pack2(a,c);
            *(uint32_t*)&g_cl[(row+8)*DMODEL + n] = pack2(bb,d);
        }
    }
}

// ============================================================================
extern "C" void kernel_launch(void* const* d_in, const int* in_sizes, int n_in,
                              void* d_out, int out_size)
{
    const float* x  = (const float*)d_in[0];
    const float* Wq = (const float*)d_in[1];
    const float* bq = (const float*)d_in[2];
    const float* Wk = (const float*)d_in[3];
    const float* bk = (const float*)d_in[4];
    const float* Wv = (const float*)d_in[5];
    const float* bv = (const float*)d_in[6];
    const float* Wp = (const float*)d_in[7];
    const float* bp = (const float*)d_in[8];
    float* out = (float*)d_out;

    split_x_kernel<<<((size_t)MR*DMODEL + 255)/256, 256>>>(x);
    prep_all_kernel<<<(NQ*DMODEL + 255)/256, 256>>>(Wq, Wk, Wv, bq, bk, bv, Wp);

    cudaFuncSetAttribute(gemm_qkv_kernel, cudaFuncAttributeMaxDynamicSharedMemorySize, GSMEM);
    cudaFuncSetAttribute(gemm_out_kernel, cudaFuncAttributeMaxDynamicSharedMemorySize, GSMEM);
    gemm_qkv_kernel<<<dim3(NQ/128, MR/128), 256, GSMEM>>>();

    cudaFuncSetAttribute(attn_mma, cudaFuncAttributeMaxDynamicSharedMemorySize, ATTN_SMEM);
    attn_mma<<<dim3(SEQ/128, BBATCH*NHEAD), 128, ATTN_SMEM>>>();

    gemm_out_kernel<<<dim3(DMODEL/128, MR/128), 256, GSMEM>>>(bp, out);
}

// round 11
// speedup vs baseline: 1.3919x; 1.3919x over previous
#include <cuda_runtime.h>
#include <cuda_bf16.h>
#include <math.h>
#include <stdint.h>

#define BBATCH 8
#define SEQ    2048
#define DMODEL 768
#define NHEAD  12
#define HD     64
#define MR     (BBATCH*SEQ)      // 16384
#define NQ     (3*DMODEL)        // 2304

typedef __nv_bfloat16 bf16;

// ---- static device scratch (no allocations allowed) ----
__device__ bf16  g_xh[(size_t)MR*DMODEL],  g_xl[(size_t)MR*DMODEL];
__device__ bf16  g_Wth[(size_t)NQ*DMODEL], g_Wtl[(size_t)NQ*DMODEL];   // [n][k] n-major
__device__ float g_bqkv[NQ];
__device__ bf16  g_Wpth[(size_t)DMODEL*DMODEL], g_Wptl[(size_t)DMODEL*DMODEL]; // [n][k]
__device__ bf16  g_qh[(size_t)MR*NQ],      g_ql[(size_t)MR*NQ];        // QKV split
__device__ bf16  g_ch[(size_t)MR*DMODEL],  g_cl[(size_t)MR*DMODEL];    // ctx split

__device__ __forceinline__ void splitf(float v, bf16 &h, bf16 &l){
    h = __float2bfloat16(v);
    l = __float2bfloat16(v - __bfloat162float(h));
}
__device__ __forceinline__ uint32_t pack2(bf16 a, bf16 b){
    union { bf16 v[2]; uint32_t u; } t; t.v[0]=a; t.v[1]=b; return t.u;
}
// Truncation split of two fp32 probs into packed bf16x2 hi + bf16x2 lo (exact 2-term).
__device__ __forceinline__ void splitp2(float p0, float p1, uint32_t &hi, uint32_t &lo){
    uint32_t u0 = __float_as_uint(p0), u1 = __float_as_uint(p1);
    hi = (u0 >> 16) | (u1 & 0xFFFF0000u);
    float r0 = p0 - __uint_as_float(u0 & 0xFFFF0000u);
    float r1 = p1 - __uint_as_float(u1 & 0xFFFF0000u);
    asm("cvt.rn.bf16x2.f32 %0, %1, %2;" : "=r"(lo) : "f"(r1), "f"(r0));
}
__device__ __forceinline__ void mma16816(float c[4], const uint32_t a[4],
                                         uint32_t b0, uint32_t b1){
    asm volatile("mma.sync.aligned.m16n8k16.row.col.f32.bf16.bf16.f32 "
        "{%0,%1,%2,%3},{%4,%5,%6,%7},{%8,%9},{%0,%1,%2,%3};"
        : "+f"(c[0]),"+f"(c[1]),"+f"(c[2]),"+f"(c[3])
        : "r"(a[0]),"r"(a[1]),"r"(a[2]),"r"(a[3]),"r"(b0),"r"(b1));
}
__device__ __forceinline__ uint32_t smem_u32(const void* p){
    uint32_t r;
    asm("{ .reg .u64 t; cvta.to.shared.u64 t, %1; cvt.u32.u64 %0, t; }" : "=r"(r) : "l"(p));
    return r;
}
__device__ __forceinline__ void cp16(uint32_t dst, const void* src){
    asm volatile("cp.async.cg.shared.global [%0], [%1], 16;" :: "r"(dst), "l"(src));
}
#define CP_COMMIT()  asm volatile("cp.async.commit_group;" ::: "memory")
#define CP_WAIT(n)   asm volatile("cp.async.wait_group %0;" :: "n"(n) : "memory")
#define LDSM4(r0,r1,r2,r3,a) \
    asm volatile("ldmatrix.sync.aligned.m8n8.x4.shared.b16 {%0,%1,%2,%3}, [%4];" \
        : "=r"(r0),"=r"(r1),"=r"(r2),"=r"(r3) : "r"(a))
#define LDSM4T(r0,r1,r2,r3,a) \
    asm volatile("ldmatrix.sync.aligned.m8n8.x4.trans.shared.b16 {%0,%1,%2,%3}, [%4];" \
        : "=r"(r0),"=r"(r1),"=r"(r2),"=r"(r3) : "r"(a))

// Fold attention score scale AND log2(e) into Wq/bq so softmax is exp2(s - m).
#define QFOLD (1.4426950408889634f / (8.0f + 1e-6f))

// ============================================================================
// Prep kernels
// ============================================================================
__global__ void split_x_kernel(const float* __restrict__ x){
    size_t i = (size_t)blockIdx.x*blockDim.x + threadIdx.x;
    if (i < (size_t)MR*DMODEL) splitf(x[i], g_xh[i], g_xl[i]);
}

__global__ void prep_all_kernel(const float* __restrict__ Wq, const float* __restrict__ Wk,
                                const float* __restrict__ Wv, const float* __restrict__ bq,
                                const float* __restrict__ bk, const float* __restrict__ bv,
                                const float* __restrict__ Wp){
    int idx = blockIdx.x*blockDim.x + threadIdx.x;
    if (idx < NQ*DMODEL){
        int n = idx / DMODEL, k = idx - n*DMODEL;
        int sec = n / DMODEL;
        int r = n - sec*DMODEL;
        int h = r >> 6, e = r & 63;
        const float* W = (sec==0) ? Wq : (sec==1 ? Wk : Wv);
        float v = W[((size_t)h*DMODEL + k)*HD + e];
        if (sec == 0) v *= QFOLD;
        splitf(v, g_Wth[idx], g_Wtl[idx]);
    }
    if (idx < DMODEL*DMODEL){
        int n = idx / DMODEL, k = idx - n*DMODEL;
        splitf(Wp[(size_t)k*DMODEL + n], g_Wpth[idx], g_Wptl[idx]);
    }
    if (idx < NQ){
        int sec = idx / DMODEL, r = idx - sec*DMODEL;
        const float* bb = (sec==0) ? bq : (sec==1 ? bk : bv);
        float v = bb[r];
        if (sec == 0) v *= QFOLD;
        g_bqkv[idx] = v;
    }
}

// ============================================================================
// Split-bf16 MMA GEMM (R6-measured version): static smem, register-staged
// prefetch, ldmatrix fragment loads. 128x128 tile, BK=32, 256 threads.
// ============================================================================
template<bool SPLIT_OUT>
__device__ __forceinline__ void gemm_core(
    const bf16* __restrict__ Ah, const bf16* __restrict__ Al,
    const bf16* __restrict__ Bth, const bf16* __restrict__ Btl,
    const float* __restrict__ bias, int K, int N,
    bf16* __restrict__ Ch, bf16* __restrict__ Cl, float* __restrict__ Cf)
{
    constexpr int SA = 40;
    __shared__ bf16 As[2][128*SA];
    __shared__ bf16 Bs[2][128*SA];
    const int tid  = threadIdx.x;
    const int lane = tid & 31, wid = tid >> 5;
    const int g = lane >> 2, t = lane & 3;
    const int wm = (wid & 1) * 64, wn = (wid >> 1) * 32;
    const size_t bm0 = (size_t)blockIdx.y * 128;
    const size_t bn0 = (size_t)blockIdx.x * 128;

    const uint32_t aAs0 = smem_u32(As[0]), aAs1 = smem_u32(As[1]);
    const uint32_t aBs0 = smem_u32(Bs[0]), aBs1 = smem_u32(Bs[1]);
    const int offA = (lane & 15)*SA + (lane >> 4)*8;
    const int offB = ((lane & 7) + (lane >> 4)*8)*SA + ((lane >> 3) & 1)*8;

    float acc[4][4][4];
    #pragma unroll
    for (int a=0;a<4;a++)
        #pragma unroll
        for (int b=0;b<4;b++)
            #pragma unroll
            for (int c=0;c<4;c++) acc[a][b][c] = 0.0f;

    const int lr = tid >> 2;
    const int lc = (tid & 3) << 3;
    uint4 pa[2][2], pb[2][2];
    #pragma unroll
    for (int i=0;i<2;i++){
        int r = lr + i*64;
        pa[0][i] = *(const uint4*)&Ah [(bm0 + r)*K + lc];
        pa[1][i] = *(const uint4*)&Al [(bm0 + r)*K + lc];
        pb[0][i] = *(const uint4*)&Bth[(bn0 + r)*K + lc];
        pb[1][i] = *(const uint4*)&Btl[(bn0 + r)*K + lc];
    }

    for (int k0 = 0; k0 < K; k0 += 32){
        __syncthreads();
        #pragma unroll
        for (int i=0;i<2;i++){
            int r = lr + i*64;
            *(uint4*)&As[0][r*SA + lc] = pa[0][i];
            *(uint4*)&As[1][r*SA + lc] = pa[1][i];
            *(uint4*)&Bs[0][r*SA + lc] = pb[0][i];
            *(uint4*)&Bs[1][r*SA + lc] = pb[1][i];
        }
        __syncthreads();
        if (k0 + 32 < K){
            #pragma unroll
            for (int i=0;i<2;i++){
                int r = lr + i*64;
                pa[0][i] = *(const uint4*)&Ah [(bm0 + r)*K + k0+32 + lc];
                pa[1][i] = *(const uint4*)&Al [(bm0 + r)*K + k0+32 + lc];
                pb[0][i] = *(const uint4*)&Bth[(bn0 + r)*K + k0+32 + lc];
                pb[1][i] = *(const uint4*)&Btl[(bn0 + r)*K + k0+32 + lc];
            }
        }
        #pragma unroll
        for (int ks = 0; ks < 32; ks += 16){
            uint32_t afh[4][4], afl[4][4];
            #pragma unroll
            for (int mt=0; mt<4; mt++){
                uint32_t adr = aAs0 + 2*((wm + mt*16)*SA + ks + offA);
                LDSM4(afh[mt][0], afh[mt][1], afh[mt][2], afh[mt][3], adr);
                adr = aAs1 + 2*((wm + mt*16)*SA + ks + offA);
                LDSM4(afl[mt][0], afl[mt][1], afl[mt][2], afl[mt][3], adr);
            }
            uint32_t bh[2][4], bl[2][4];
            #pragma unroll
            for (int np=0; np<2; np++){
                uint32_t adr = aBs0 + 2*((wn + np*16)*SA + ks + offB);
                LDSM4(bh[np][0], bh[np][1], bh[np][2], bh[np][3], adr);
                adr = aBs1 + 2*((wn + np*16)*SA + ks + offB);
                LDSM4(bl[np][0], bl[np][1], bl[np][2], bl[np][3], adr);
            }
            #pragma unroll
            for (int np=0; np<2; np++){
                #pragma unroll
                for (int hf=0; hf<2; hf++){
                    int nt = np*2 + hf;
                    uint32_t bh0 = bh[np][2*hf], bh1 = bh[np][2*hf+1];
                    uint32_t bl0 = bl[np][2*hf], bl1 = bl[np][2*hf+1];
                    #pragma unroll
                    for (int mt=0; mt<4; mt++){
                        mma16816(acc[mt][nt], afh[mt], bh0, bh1);
                        mma16816(acc[mt][nt], afh[mt], bl0, bl1);
                        mma16816(acc[mt][nt], afl[mt], bh0, bh1);
                    }
                }
            }
        }
    }

    #pragma unroll
    for (int mt=0; mt<4; mt++){
        #pragma unroll
        for (int nt=0; nt<4; nt++){
            size_t n = bn0 + wn + nt*8 + 2*t;
            float b0v = bias[n], b1v = bias[n+1];
            size_t m = bm0 + wm + mt*16 + g;
            float v00 = acc[mt][nt][0] + b0v, v01 = acc[mt][nt][1] + b1v;
            float v10 = acc[mt][nt][2] + b0v, v11 = acc[mt][nt][3] + b1v;
            if (SPLIT_OUT){
                bf16 h0,l0,h1,l1;
                splitf(v00,h0,l0); splitf(v01,h1,l1);
                *(uint32_t*)&Ch[m*N + n] = pack2(h0,h1);
                *(uint32_t*)&Cl[m*N + n] = pack2(l0,l1);
                splitf(v10,h0,l0); splitf(v11,h1,l1);
                *(uint32_t*)&Ch[(m+8)*N + n] = pack2(h0,h1);
                *(uint32_t*)&Cl[(m+8)*N + n] = pack2(l0,l1);
            } else {
                float2 fa; fa.x = v00; fa.y = v01;
                float2 fb; fb.x = v10; fb.y = v11;
                *(float2*)&Cf[m*N + n]     = fa;
                *(float2*)&Cf[(m+8)*N + n] = fb;
            }
        }
    }
}

__global__ __launch_bounds__(256) void gemm_qkv_kernel(){
    gemm_core<true>(g_xh, g_xl, g_Wth, g_Wtl, g_bqkv, DMODEL, NQ, g_qh, g_ql, nullptr);
}
__global__ __launch_bounds__(256) void gemm_out_kernel(const float* __restrict__ bp,
                                                       float* __restrict__ out){
    gemm_core<false>(g_ch, g_cl, g_Wpth, g_Wptl, bp, DMODEL, DMODEL, nullptr, nullptr, out);
}

// ============================================================================
// Flash attention: 128-q-row blocks, ldmatrix frags, cp.async double-buffered K/V.
// Q pre-scaled by QFOLD (in weights) -> softmax = exp2(s - m), no score scaling.
// ============================================================================
#define KV_ARR   (64*72)
#define KV_ARRB  (KV_ARR*2)
#define KV_BUFB  (4*KV_ARRB)
#define ATTN_SMEM (2*128*72*2 + 2*KV_BUFB)   // 110592

__global__ __launch_bounds__(128) void attn_mma(){
    extern __shared__ __align__(16) char smraw[];
    bf16* Qh = (bf16*)smraw;               // [128][72]
    bf16* Ql = Qh + 128*72;
    const uint32_t aQh = smem_u32(Qh), aQl = smem_u32(Ql);
    const uint32_t aKV = aQh + 2*2*128*72;

    const int tid  = threadIdx.x;
    const int lane = tid & 31, wid = tid >> 5;
    const int g = lane >> 2, t = lane & 3;
    const int b = blockIdx.y / NHEAD, h = blockIdx.y % NHEAD;
    const int q0 = blockIdx.x * 128;
    const size_t rowbase = (size_t)b*SEQ*NQ + (size_t)h*HD;

    #pragma unroll
    for (int i=0;i<8;i++){
        int v = tid + i*128;
        int r = v >> 3, c = (v & 7) << 3;
        *(uint4*)&Qh[r*72 + c] = *(const uint4*)&g_qh[rowbase + (size_t)(q0+r)*NQ + c];
        *(uint4*)&Ql[r*72 + c] = *(const uint4*)&g_ql[rowbase + (size_t)(q0+r)*NQ + c];
    }

    auto issue_kv = [&](int it, int bufIdx){
        uint32_t base = aKV + bufIdx*KV_BUFB;
        #pragma unroll
        for (int i=0;i<4;i++){
            int v = tid + i*128;
            int r = v >> 3, c = (v & 7) << 3;
            size_t grow = rowbase + (size_t)(it*64 + r)*NQ;
            uint32_t doff = 2*(r*72 + c);
            cp16(base + 0*KV_ARRB + doff, &g_qh[grow +   DMODEL + c]);
            cp16(base + 1*KV_ARRB + doff, &g_ql[grow +   DMODEL + c]);
            cp16(base + 2*KV_ARRB + doff, &g_qh[grow + 2*DMODEL + c]);
            cp16(base + 3*KV_ARRB + doff, &g_ql[grow + 2*DMODEL + c]);
        }
        CP_COMMIT();
    };

    const int offA = (lane & 15)*72 + (lane >> 4)*8;
    const int offB = ((lane & 7) + (lane >> 4)*8)*72 + ((lane >> 3) & 1)*8;
    const int offV = ((lane & 7) + ((lane >> 3) & 1)*8)*72 + (lane >> 4)*8;

    float m[2][2], l[2][2], o[2][8][4];
    #pragma unroll
    for (int mt=0;mt<2;mt++){
        m[mt][0]=-1e30f; m[mt][1]=-1e30f; l[mt][0]=0.0f; l[mt][1]=0.0f;
        #pragma unroll
        for (int e=0;e<8;e++){ o[mt][e][0]=0; o[mt][e][1]=0; o[mt][e][2]=0; o[mt][e][3]=0; }
    }
    const int NT = SEQ/64;

    issue_kv(0, 0);

    for (int it = 0; it < NT; it++){
        const int buf = it & 1;
        __syncthreads();
        if (it + 1 < NT){ issue_kv(it + 1, buf ^ 1); CP_WAIT(1); }
        else            { CP_WAIT(0); }
        __syncthreads();

        const uint32_t aKh = aKV + buf*KV_BUFB;
        const uint32_t aKl = aKh + KV_ARRB;
        const uint32_t aVh = aKl + KV_ARRB;
        const uint32_t aVl = aVh + KV_ARRB;

        // ---- S = Q K^T (3-term split), 2 m-tiles per warp ----
        float s[2][8][4];
        #pragma unroll
        for (int mt=0;mt<2;mt++)
            #pragma unroll
            for (int nt=0;nt<8;nt++){ s[mt][nt][0]=0; s[mt][nt][1]=0; s[mt][nt][2]=0; s[mt][nt][3]=0; }

        #pragma unroll
        for (int ks=0; ks<64; ks+=16){
            uint32_t ah[2][4], al[2][4];
            #pragma unroll
            for (int mt=0; mt<2; mt++){
                uint32_t adr = aQh + 2*((wid*32 + mt*16)*72 + ks + offA);
                LDSM4(ah[mt][0], ah[mt][1], ah[mt][2], ah[mt][3], adr);
                adr = aQl + 2*((wid*32 + mt*16)*72 + ks + offA);
                LDSM4(al[mt][0], al[mt][1], al[mt][2], al[mt][3], adr);
            }
            #pragma unroll
            for (int np=0; np<4; np++){
                uint32_t kh0,kh1,kh2,kh3, kl0,kl1,kl2,kl3;
                uint32_t adr = aKh + 2*((np*16)*72 + ks + offB);
                LDSM4(kh0,kh1,kh2,kh3, adr);
                adr = aKl + 2*((np*16)*72 + ks + offB);
                LDSM4(kl0,kl1,kl2,kl3, adr);
                #pragma unroll
                for (int mt=0; mt<2; mt++){
                    mma16816(s[mt][2*np  ], ah[mt], kh0, kh1);
                    mma16816(s[mt][2*np  ], ah[mt], kl0, kl1);
                    mma16816(s[mt][2*np  ], al[mt], kh0, kh1);
                    mma16816(s[mt][2*np+1], ah[mt], kh2, kh3);
                    mma16816(s[mt][2*np+1], ah[mt], kl2, kl3);
                    mma16816(s[mt][2*np+1], al[mt], kh2, kh3);
                }
            }
        }

        // ---- Online softmax per m-tile (base-2 domain, scores pre-scaled) ----
        uint32_t ph01[2][8], ph23[2][8], pl01[2][8], pl23[2][8];
        #pragma unroll
        for (int mt=0; mt<2; mt++){
            float rm0 = -1e30f, rm1 = -1e30f;
            #pragma unroll
            for (int nt=0;nt<8;nt++){
                rm0 = fmaxf(rm0, fmaxf(s[mt][nt][0], s[mt][nt][1]));
                rm1 = fmaxf(rm1, fmaxf(s[mt][nt][2], s[mt][nt][3]));
            }
            rm0 = fmaxf(rm0, __shfl_xor_sync(0xffffffffu, rm0, 1));
            rm0 = fmaxf(rm0, __shfl_xor_sync(0xffffffffu, rm0, 2));
            rm1 = fmaxf(rm1, __shfl_xor_sync(0xffffffffu, rm1, 1));
            rm1 = fmaxf(rm1, __shfl_xor_sync(0xffffffffu, rm1, 2));
            float mn0 = fmaxf(m[mt][0], rm0), mn1 = fmaxf(m[mt][1], rm1);
            float cr0 = exp2f(m[mt][0] - mn0), cr1 = exp2f(m[mt][1] - mn1);
            m[mt][0] = mn0; m[mt][1] = mn1;

            float rs0 = 0.0f, rs1 = 0.0f;
            #pragma unroll
            for (int nt=0;nt<8;nt++){
                float p0 = exp2f(s[mt][nt][0]-mn0), p1 = exp2f(s[mt][nt][1]-mn0);
                float p2 = exp2f(s[mt][nt][2]-mn1), p3 = exp2f(s[mt][nt][3]-mn1);
                rs0 += p0+p1; rs1 += p2+p3;
                splitp2(p0, p1, ph01[mt][nt], pl01[mt][nt]);
                splitp2(p2, p3, ph23[mt][nt], pl23[mt][nt]);
            }
            rs0 += __shfl_xor_sync(0xffffffffu, rs0, 1);
            rs0 += __shfl_xor_sync(0xffffffffu, rs0, 2);
            rs1 += __shfl_xor_sync(0xffffffffu, rs1, 1);
            rs1 += __shfl_xor_sync(0xffffffffu, rs1, 2);
            l[mt][0] = l[mt][0]*cr0 + rs0; l[mt][1] = l[mt][1]*cr1 + rs1;
            #pragma unroll
            for (int e=0;e<8;e++){
                o[mt][e][0]*=cr0; o[mt][e][1]*=cr0; o[mt][e][2]*=cr1; o[mt][e][3]*=cr1;
            }
        }

        // ---- O += P @ V ----
        #pragma unroll
        for (int j2=0; j2<4; j2++){
            uint32_t aP[2][4], aPl[2][4];
            #pragma unroll
            for (int mt=0; mt<2; mt++){
                aP [mt][0]=ph01[mt][2*j2];   aP [mt][1]=ph23[mt][2*j2];
                aP [mt][2]=ph01[mt][2*j2+1]; aP [mt][3]=ph23[mt][2*j2+1];
                aPl[mt][0]=pl01[mt][2*j2];   aPl[mt][1]=pl23[mt][2*j2];
                aPl[mt][2]=pl01[mt][2*j2+1]; aPl[mt][3]=pl23[mt][2*j2+1];
            }
            #pragma unroll
            for (int ep=0; ep<4; ep++){
                uint32_t vh0,vh1,vh2,vh3, vl0,vl1,vl2,vl3;
                uint32_t adr = aVh + 2*((j2*16)*72 + ep*16 + offV);
                LDSM4T(vh0,vh1,vh2,vh3, adr);
                adr = aVl + 2*((j2*16)*72 + ep*16 + offV);
                LDSM4T(vl0,vl1,vl2,vl3, adr);
                #pragma unroll
                for (int mt=0; mt<2; mt++){
                    mma16816(o[mt][2*ep  ], aP[mt],  vh0, vh1);
                    mma16816(o[mt][2*ep  ], aP[mt],  vl0, vl1);
                    mma16816(o[mt][2*ep  ], aPl[mt], vh0, vh1);
                    mma16816(o[mt][2*ep+1], aP[mt],  vh2, vh3);
                    mma16816(o[mt][2*ep+1], aP[mt],  vl2, vl3);
                    mma16816(o[mt][2*ep+1], aPl[mt], vh2, vh3);
                }
            }
        }
    }

    // ---- Normalize, split, write ctx hi/lo ----
    #pragma unroll
    for (int mt=0; mt<2; mt++){
        float i0 = 1.0f/l[mt][0], i1 = 1.0f/l[mt][1];
        size_t row = (size_t)b*SEQ + q0 + wid*32 + mt*16 + g;
        #pragma unroll
        for (int et=0; et<8; et++){
            int n = h*HD + et*8 + 2*t;
            float v00 = o[mt][et][0]*i0, v01 = o[mt][et][1]*i0;
            float v10 = o[mt][et][2]*i1, v11 = o[mt][et][3]*i1;
            bf16 a,bb,c,d;
            splitf(v00,a,bb); splitf(v01,c,d);
            *(uint32_t*)&g_ch[row*DMODEL + n] = pack2(a,c);
            *(uint32_t*)&g_cl[row*DMODEL + n] = pack2(bb,d);
            splitf(v10,a,bb); splitf(v11,c,d);
            *(uint32_t*)&g_ch[(row+8)*DMODEL + n] = pack2(a,c);
            *(uint32_t*)&g_cl[(row+8)*DMODEL + n] = pack2(bb,d);
        }
    }
}

// ============================================================================
extern "C" void kernel_launch(void* const* d_in, const int* in_sizes, int n_in,
                              void* d_out, int out_size)
{
    const float* x  = (const float*)d_in[0];
    const float* Wq = (const float*)d_in[1];
    const float* bq = (const float*)d_in[2];
    const float* Wk = (const float*)d_in[3];
    const float* bk = (const float*)d_in[4];
    const float* Wv = (const float*)d_in[5];
    const float* bv = (const float*)d_in[6];
    const float* Wp = (const float*)d_in[7];
    const float* bp = (const float*)d_in[8];
    float* out = (float*)d_out;

    split_x_kernel<<<((size_t)MR*DMODEL + 255)/256, 256>>>(x);
    prep_all_kernel<<<(NQ*DMODEL + 255)/256, 256>>>(Wq, Wk, Wv, bq, bk, bv, Wp);
    gemm_qkv_kernel<<<dim3(NQ/128, MR/128), 256>>>();

    cudaFuncSetAttribute(attn_mma, cudaFuncAttributeMaxDynamicSharedMemorySize, ATTN_SMEM);
    attn_mma<<<dim3(SEQ/128, BBATCH*NHEAD), 128, ATTN_SMEM>>>();

    gemm_out_kernel<<<dim3(DMODEL/128, MR/128), 256>>>(bp, out);
}

// round 12
// speedup vs baseline: 1.5741x; 1.1310x over previous
#include <cuda_runtime.h>
#include <cuda_bf16.h>
#include <cuda_fp16.h>
#include <math.h>
#include <stdint.h>

#define BBATCH 8
#define SEQ    2048
#define DMODEL 768
#define NHEAD  12
#define HD     64
#define MR     (BBATCH*SEQ)      // 16384
#define NQ     (3*DMODEL)        // 2304

typedef __nv_bfloat16 bf16;

// ---- static device scratch (no allocations allowed) ----
__device__ bf16  g_xh[(size_t)MR*DMODEL],  g_xl[(size_t)MR*DMODEL];
__device__ bf16  g_Wth[(size_t)NQ*DMODEL], g_Wtl[(size_t)NQ*DMODEL];   // [n][k] n-major
__device__ float g_bqkv[NQ];
__device__ bf16  g_Wpth[(size_t)DMODEL*DMODEL], g_Wptl[(size_t)DMODEL*DMODEL]; // [n][k]
__device__ __half g_qh[(size_t)MR*NQ],     g_ql[(size_t)MR*NQ];        // QKV fp16 hi/lo
__device__ bf16  g_ch[(size_t)MR*DMODEL],  g_cl[(size_t)MR*DMODEL];    // ctx split (bf16)

__device__ __forceinline__ void splitf(float v, bf16 &h, bf16 &l){
    h = __float2bfloat16(v);
    l = __float2bfloat16(v - __bfloat162float(h));
}
__device__ __forceinline__ uint32_t pack2(bf16 a, bf16 b){
    union { bf16 v[2]; uint32_t u; } t; t.v[0]=a; t.v[1]=b; return t.u;
}
__device__ __forceinline__ void splith(float v, __half &h, __half &l){
    h = __float2half_rn(v);
    l = __float2half_rn(v - __half2float(h));
}
__device__ __forceinline__ uint32_t pack2h(__half a, __half b){
    union { __half v[2]; uint32_t u; } t; t.v[0]=a; t.v[1]=b; return t.u;
}
// fp16 2-term split of two probs -> packed f16x2 hi + f16x2 lo
__device__ __forceinline__ void splitp2h(float p0, float p1, uint32_t &hi, uint32_t &lo){
    __half2 h2 = __floats2half2_rn(p0, p1);
    float2 hf = __half22float2(h2);
    __half2 l2 = __floats2half2_rn(p0 - hf.x, p1 - hf.y);
    hi = *(uint32_t*)&h2; lo = *(uint32_t*)&l2;
}
__device__ __forceinline__ void mma16816(float c[4], const uint32_t a[4],
                                         uint32_t b0, uint32_t b1){
    asm volatile("mma.sync.aligned.m16n8k16.row.col.f32.bf16.bf16.f32 "
        "{%0,%1,%2,%3},{%4,%5,%6,%7},{%8,%9},{%0,%1,%2,%3};"
        : "+f"(c[0]),"+f"(c[1]),"+f"(c[2]),"+f"(c[3])
        : "r"(a[0]),"r"(a[1]),"r"(a[2]),"r"(a[3]),"r"(b0),"r"(b1));
}
__device__ __forceinline__ void mma16816h(float c[4], const uint32_t a[4],
                                          uint32_t b0, uint32_t b1){
    asm volatile("mma.sync.aligned.m16n8k16.row.col.f32.f16.f16.f32 "
        "{%0,%1,%2,%3},{%4,%5,%6,%7},{%8,%9},{%0,%1,%2,%3};"
        : "+f"(c[0]),"+f"(c[1]),"+f"(c[2]),"+f"(c[3])
        : "r"(a[0]),"r"(a[1]),"r"(a[2]),"r"(a[3]),"r"(b0),"r"(b1));
}
__device__ __forceinline__ uint32_t smem_u32(const void* p){
    uint32_t r;
    asm("{ .reg .u64 t; cvta.to.shared.u64 t, %1; cvt.u32.u64 %0, t; }" : "=r"(r) : "l"(p));
    return r;
}
__device__ __forceinline__ void cp16(uint32_t dst, const void* src){
    asm volatile("cp.async.cg.shared.global [%0], [%1], 16;" :: "r"(dst), "l"(src));
}
#define CP_COMMIT()  asm volatile("cp.async.commit_group;" ::: "memory")
#define CP_WAIT(n)   asm volatile("cp.async.wait_group %0;" :: "n"(n) : "memory")
#define LDSM4(r0,r1,r2,r3,a) \
    asm volatile("ldmatrix.sync.aligned.m8n8.x4.shared.b16 {%0,%1,%2,%3}, [%4];" \
        : "=r"(r0),"=r"(r1),"=r"(r2),"=r"(r3) : "r"(a))
#define LDSM4T(r0,r1,r2,r3,a) \
    asm volatile("ldmatrix.sync.aligned.m8n8.x4.trans.shared.b16 {%0,%1,%2,%3}, [%4];" \
        : "=r"(r0),"=r"(r1),"=r"(r2),"=r"(r3) : "r"(a))

// Fold attention score scale AND log2(e) into Wq/bq so softmax is exp2(s - m).
#define QFOLD (1.4426950408889634f / (8.0f + 1e-6f))

// ============================================================================
// Prep kernels
// ============================================================================
__global__ void split_x_kernel(const float* __restrict__ x){
    size_t i = (size_t)blockIdx.x*blockDim.x + threadIdx.x;
    if (i < (size_t)MR*DMODEL) splitf(x[i], g_xh[i], g_xl[i]);
}

__global__ void prep_all_kernel(const float* __restrict__ Wq, const float* __restrict__ Wk,
                                const float* __restrict__ Wv, const float* __restrict__ bq,
                                const float* __restrict__ bk, const float* __restrict__ bv,
                                const float* __restrict__ Wp){
    int idx = blockIdx.x*blockDim.x + threadIdx.x;
    if (idx < NQ*DMODEL){
        int n = idx / DMODEL, k = idx - n*DMODEL;
        int sec = n / DMODEL;
        int r = n - sec*DMODEL;
        int h = r >> 6, e = r & 63;
        const float* W = (sec==0) ? Wq : (sec==1 ? Wk : Wv);
        float v = W[((size_t)h*DMODEL + k)*HD + e];
        if (sec == 0) v *= QFOLD;
        splitf(v, g_Wth[idx], g_Wtl[idx]);
    }
    if (idx < DMODEL*DMODEL){
        int n = idx / DMODEL, k = idx - n*DMODEL;
        splitf(Wp[(size_t)k*DMODEL + n], g_Wpth[idx], g_Wptl[idx]);
    }
    if (idx < NQ){
        int sec = idx / DMODEL, r = idx - sec*DMODEL;
        const float* bb = (sec==0) ? bq : (sec==1 ? bk : bv);
        float v = bb[r];
        if (sec == 0) v *= QFOLD;
        g_bqkv[idx] = v;
    }
}

// ============================================================================
// Split-bf16 MMA GEMM (R6-measured structure): static smem, register-staged
// prefetch, ldmatrix fragment loads. 128x128 tile, BK=32, 256 threads.
// SPLIT_OUT=true writes fp16 hi/lo (for attention); else fp32 + bias to Cf.
// ============================================================================
template<bool SPLIT_OUT>
__device__ __forceinline__ void gemm_core(
    const bf16* __restrict__ Ah, const bf16* __restrict__ Al,
    const bf16* __restrict__ Bth, const bf16* __restrict__ Btl,
    const float* __restrict__ bias, int K, int N,
    __half* __restrict__ Ch, __half* __restrict__ Cl, float* __restrict__ Cf)
{
    constexpr int SA = 40;
    __shared__ bf16 As[2][128*SA];
    __shared__ bf16 Bs[2][128*SA];
    const int tid  = threadIdx.x;
    const int lane = tid & 31, wid = tid >> 5;
    const int g = lane >> 2, t = lane & 3;
    const int wm = (wid & 1) * 64, wn = (wid >> 1) * 32;
    const size_t bm0 = (size_t)blockIdx.y * 128;
    const size_t bn0 = (size_t)blockIdx.x * 128;

    const uint32_t aAs0 = smem_u32(As[0]), aAs1 = smem_u32(As[1]);
    const uint32_t aBs0 = smem_u32(Bs[0]), aBs1 = smem_u32(Bs[1]);
    const int offA = (lane & 15)*SA + (lane >> 4)*8;
    const int offB = ((lane & 7) + (lane >> 4)*8)*SA + ((lane >> 3) & 1)*8;

    float acc[4][4][4];
    #pragma unroll
    for (int a=0;a<4;a++)
        #pragma unroll
        for (int b=0;b<4;b++)
            #pragma unroll
            for (int c=0;c<4;c++) acc[a][b][c] = 0.0f;

    const int lr = tid >> 2;
    const int lc = (tid & 3) << 3;
    uint4 pa[2][2], pb[2][2];
    #pragma unroll
    for (int i=0;i<2;i++){
        int r = lr + i*64;
        pa[0][i] = *(const uint4*)&Ah [(bm0 + r)*K + lc];
        pa[1][i] = *(const uint4*)&Al [(bm0 + r)*K + lc];
        pb[0][i] = *(const uint4*)&Bth[(bn0 + r)*K + lc];
        pb[1][i] = *(const uint4*)&Btl[(bn0 + r)*K + lc];
    }

    for (int k0 = 0; k0 < K; k0 += 32){
        __syncthreads();
        #pragma unroll
        for (int i=0;i<2;i++){
            int r = lr + i*64;
            *(uint4*)&As[0][r*SA + lc] = pa[0][i];
            *(uint4*)&As[1][r*SA + lc] = pa[1][i];
            *(uint4*)&Bs[0][r*SA + lc] = pb[0][i];
            *(uint4*)&Bs[1][r*SA + lc] = pb[1][i];
        }
        __syncthreads();
        if (k0 + 32 < K){
            #pragma unroll
            for (int i=0;i<2;i++){
                int r = lr + i*64;
                pa[0][i] = *(const uint4*)&Ah [(bm0 + r)*K + k0+32 + lc];
                pa[1][i] = *(const uint4*)&Al [(bm0 + r)*K + k0+32 + lc];
                pb[0][i] = *(const uint4*)&Bth[(bn0 + r)*K + k0+32 + lc];
                pb[1][i] = *(const uint4*)&Btl[(bn0 + r)*K + k0+32 + lc];
            }
        }
        #pragma unroll
        for (int ks = 0; ks < 32; ks += 16){
            uint32_t afh[4][4], afl[4][4];
            #pragma unroll
            for (int mt=0; mt<4; mt++){
                uint32_t adr = aAs0 + 2*((wm + mt*16)*SA + ks + offA);
                LDSM4(afh[mt][0], afh[mt][1], afh[mt][2], afh[mt][3], adr);
                adr = aAs1 + 2*((wm + mt*16)*SA + ks + offA);
                LDSM4(afl[mt][0], afl[mt][1], afl[mt][2], afl[mt][3], adr);
            }
            uint32_t bh[2][4], bl[2][4];
            #pragma unroll
            for (int np=0; np<2; np++){
                uint32_t adr = aBs0 + 2*((wn + np*16)*SA + ks + offB);
                LDSM4(bh[np][0], bh[np][1], bh[np][2], bh[np][3], adr);
                adr = aBs1 + 2*((wn + np*16)*SA + ks + offB);
                LDSM4(bl[np][0], bl[np][1], bl[np][2], bl[np][3], adr);
            }
            #pragma unroll
            for (int np=0; np<2; np++){
                #pragma unroll
                for (int hf=0; hf<2; hf++){
                    int nt = np*2 + hf;
                    uint32_t bh0 = bh[np][2*hf], bh1 = bh[np][2*hf+1];
                    uint32_t bl0 = bl[np][2*hf], bl1 = bl[np][2*hf+1];
                    #pragma unroll
                    for (int mt=0; mt<4; mt++){
                        mma16816(acc[mt][nt], afh[mt], bh0, bh1);
                        mma16816(acc[mt][nt], afh[mt], bl0, bl1);
                        mma16816(acc[mt][nt], afl[mt], bh0, bh1);
                    }
                }
            }
        }
    }

    #pragma unroll
    for (int mt=0; mt<4; mt++){
        #pragma unroll
        for (int nt=0; nt<4; nt++){
            size_t n = bn0 + wn + nt*8 + 2*t;
            float b0v = bias[n], b1v = bias[n+1];
            size_t m = bm0 + wm + mt*16 + g;
            float v00 = acc[mt][nt][0] + b0v, v01 = acc[mt][nt][1] + b1v;
            float v10 = acc[mt][nt][2] + b0v, v11 = acc[mt][nt][3] + b1v;
            if (SPLIT_OUT){
                __half h0,l0,h1,l1;
                splith(v00,h0,l0); splith(v01,h1,l1);
                *(uint32_t*)&Ch[m*N + n] = pack2h(h0,h1);
                *(uint32_t*)&Cl[m*N + n] = pack2h(l0,l1);
                splith(v10,h0,l0); splith(v11,h1,l1);
                *(uint32_t*)&Ch[(m+8)*N + n] = pack2h(h0,h1);
                *(uint32_t*)&Cl[(m+8)*N + n] = pack2h(l0,l1);
            } else {
                float2 fa; fa.x = v00; fa.y = v01;
                float2 fb; fb.x = v10; fb.y = v11;
                *(float2*)&Cf[m*N + n]     = fa;
                *(float2*)&Cf[(m+8)*N + n] = fb;
            }
        }
    }
}

__global__ __launch_bounds__(256) void gemm_qkv_kernel(){
    gemm_core<true>(g_xh, g_xl, g_Wth, g_Wtl, g_bqkv, DMODEL, NQ, g_qh, g_ql, nullptr);
}
__global__ __launch_bounds__(256) void gemm_out_kernel(const float* __restrict__ bp,
                                                       float* __restrict__ out){
    gemm_core<false>(g_ch, g_cl, g_Wpth, g_Wptl, bp, DMODEL, DMODEL, nullptr, nullptr, out);
}

// ============================================================================
// Flash attention, fp16 2-term: S = Qh*Kh + Ql*Kh ; O += Ph*Vh + Pl*Vh.
// 128-q-row blocks, ldmatrix frags, cp.async double-buffered K/V (hi only).
// Q pre-scaled by QFOLD -> softmax = exp2(s - m).
// ============================================================================
#define KV_ARR   (64*72)
#define KV_ARRB  (KV_ARR*2)
#define KV_BUFB  (2*KV_ARRB)                 // Kh, Vh only
#define ATTN_SMEM (2*128*72*2 + 2*KV_BUFB)   // 73728

__global__ __launch_bounds__(128) void attn_mma(){
    extern __shared__ __align__(16) char smraw[];
    __half* Qh = (__half*)smraw;           // [128][72] fp16
    __half* Ql = Qh + 128*72;
    const uint32_t aQh = smem_u32(Qh), aQl = smem_u32(Ql);
    const uint32_t aKV = aQh + 2*2*128*72;

    const int tid  = threadIdx.x;
    const int lane = tid & 31, wid = tid >> 5;
    const int g = lane >> 2, t = lane & 3;
    const int b = blockIdx.y / NHEAD, h = blockIdx.y % NHEAD;
    const int q0 = blockIdx.x * 128;
    const size_t rowbase = (size_t)b*SEQ*NQ + (size_t)h*HD;

    #pragma unroll
    for (int i=0;i<8;i++){
        int v = tid + i*128;
        int r = v >> 3, c = (v & 7) << 3;
        *(uint4*)&Qh[r*72 + c] = *(const uint4*)&g_qh[rowbase + (size_t)(q0+r)*NQ + c];
        *(uint4*)&Ql[r*72 + c] = *(const uint4*)&g_ql[rowbase + (size_t)(q0+r)*NQ + c];
    }

    auto issue_kv = [&](int it, int bufIdx){
        uint32_t base = aKV + bufIdx*KV_BUFB;
        #pragma unroll
        for (int i=0;i<4;i++){
            int v = tid + i*128;
            int r = v >> 3, c = (v & 7) << 3;
            size_t grow = rowbase + (size_t)(it*64 + r)*NQ;
            uint32_t doff = 2*(r*72 + c);
            cp16(base + 0*KV_ARRB + doff, &g_qh[grow +   DMODEL + c]);   // Kh
            cp16(base + 1*KV_ARRB + doff, &g_qh[grow + 2*DMODEL + c]);   // Vh
        }
        CP_COMMIT();
    };

    const int offA = (lane & 15)*72 + (lane >> 4)*8;
    const int offB = ((lane & 7) + (lane >> 4)*8)*72 + ((lane >> 3) & 1)*8;
    const int offV = ((lane & 7) + ((lane >> 3) & 1)*8)*72 + (lane >> 4)*8;

    float m[2][2], l[2][2], o[2][8][4];
    #pragma unroll
    for (int mt=0;mt<2;mt++){
        m[mt][0]=-1e30f; m[mt][1]=-1e30f; l[mt][0]=0.0f; l[mt][1]=0.0f;
        #pragma unroll
        for (int e=0;e<8;e++){ o[mt][e][0]=0; o[mt][e][1]=0; o[mt][e][2]=0; o[mt][e][3]=0; }
    }
    const int NT = SEQ/64;

    issue_kv(0, 0);

    for (int it = 0; it < NT; it++){
        const int buf = it & 1;
        __syncthreads();
        if (it + 1 < NT){ issue_kv(it + 1, buf ^ 1); CP_WAIT(1); }
        else            { CP_WAIT(0); }
        __syncthreads();

        const uint32_t aKh = aKV + buf*KV_BUFB;
        const uint32_t aVh = aKh + KV_ARRB;

        // ---- S = Q K^T (fp16 2-term), 2 m-tiles per warp ----
        float s[2][8][4];
        #pragma unroll
        for (int mt=0;mt<2;mt++)
            #pragma unroll
            for (int nt=0;nt<8;nt++){ s[mt][nt][0]=0; s[mt][nt][1]=0; s[mt][nt][2]=0; s[mt][nt][3]=0; }

        #pragma unroll
        for (int ks=0; ks<64; ks+=16){
            uint32_t ah[2][4], al[2][4];
            #pragma unroll
            for (int mt=0; mt<2; mt++){
                uint32_t adr = aQh + 2*((wid*32 + mt*16)*72 + ks + offA);
                LDSM4(ah[mt][0], ah[mt][1], ah[mt][2], ah[mt][3], adr);
                adr = aQl + 2*((wid*32 + mt*16)*72 + ks + offA);
                LDSM4(al[mt][0], al[mt][1], al[mt][2], al[mt][3], adr);
            }
            #pragma unroll
            for (int np=0; np<4; np++){
                uint32_t kh0,kh1,kh2,kh3;
                uint32_t adr = aKh + 2*((np*16)*72 + ks + offB);
                LDSM4(kh0,kh1,kh2,kh3, adr);
                #pragma unroll
                for (int mt=0; mt<2; mt++){
                    mma16816h(s[mt][2*np  ], ah[mt], kh0, kh1);
                    mma16816h(s[mt][2*np  ], al[mt], kh0, kh1);
                    mma16816h(s[mt][2*np+1], ah[mt], kh2, kh3);
                    mma16816h(s[mt][2*np+1], al[mt], kh2, kh3);
                }
            }
        }

        // ---- Online softmax per m-tile (base-2 domain, scores pre-scaled) ----
        uint32_t ph01[2][8], ph23[2][8], pl01[2][8], pl23[2][8];
        #pragma unroll
        for (int mt=0; mt<2; mt++){
            float rm0 = -1e30f, rm1 = -1e30f;
            #pragma unroll
            for (int nt=0;nt<8;nt++){
                rm0 = fmaxf(rm0, fmaxf(s[mt][nt][0], s[mt][nt][1]));
                rm1 = fmaxf(rm1, fmaxf(s[mt][nt][2], s[mt][nt][3]));
            }
            rm0 = fmaxf(rm0, __shfl_xor_sync(0xffffffffu, rm0, 1));
            rm0 = fmaxf(rm0, __shfl_xor_sync(0xffffffffu, rm0, 2));
            rm1 = fmaxf(rm1, __shfl_xor_sync(0xffffffffu, rm1, 1));
            rm1 = fmaxf(rm1, __shfl_xor_sync(0xffffffffu, rm1, 2));
            float mn0 = fmaxf(m[mt][0], rm0), mn1 = fmaxf(m[mt][1], rm1);
            float cr0 = exp2f(m[mt][0] - mn0), cr1 = exp2f(m[mt][1] - mn1);
            m[mt][0] = mn0; m[mt][1] = mn1;

            float rs0 = 0.0f, rs1 = 0.0f;
            #pragma unroll
            for (int nt=0;nt<8;nt++){
                float p0 = exp2f(s[mt][nt][0]-mn0), p1 = exp2f(s[mt][nt][1]-mn0);
                float p2 = exp2f(s[mt][nt][2]-mn1), p3 = exp2f(s[mt][nt][3]-mn1);
                rs0 += p0+p1; rs1 += p2+p3;
                splitp2h(p0, p1, ph01[mt][nt], pl01[mt][nt]);
                splitp2h(p2, p3, ph23[mt][nt], pl23[mt][nt]);
            }
            rs0 += __shfl_xor_sync(0xffffffffu, rs0, 1);
            rs0 += __shfl_xor_sync(0xffffffffu, rs0, 2);
            rs1 += __shfl_xor_sync(0xffffffffu, rs1, 1);
            rs1 += __shfl_xor_sync(0xffffffffu, rs1, 2);
            l[mt][0] = l[mt][0]*cr0 + rs0; l[mt][1] = l[mt][1]*cr1 + rs1;
            #pragma unroll
            for (int e=0;e<8;e++){
                o[mt][e][0]*=cr0; o[mt][e][1]*=cr0; o[mt][e][2]*=cr1; o[mt][e][3]*=cr1;
            }
        }

        // ---- O += P @ V (fp16 2-term) ----
        #pragma unroll
        for (int j2=0; j2<4; j2++){
            uint32_t aP[2][4], aPl[2][4];
            #pragma unroll
            for (int mt=0; mt<2; mt++){
                aP [mt][0]=ph01[mt][2*j2];   aP [mt][1]=ph23[mt][2*j2];
                aP [mt][2]=ph01[mt][2*j2+1]; aP [mt][3]=ph23[mt][2*j2+1];
                aPl[mt][0]=pl01[mt][2*j2];   aPl[mt][1]=pl23[mt][2*j2];
                aPl[mt][2]=pl01[mt][2*j2+1]; aPl[mt][3]=pl23[mt][2*j2+1];
            }
            #pragma unroll
            for (int ep=0; ep<4; ep++){
                uint32_t vh0,vh1,vh2,vh3;
                uint32_t adr = aVh + 2*((j2*16)*72 + ep*16 + offV);
                LDSM4T(vh0,vh1,vh2,vh3, adr);
                #pragma unroll
                for (int mt=0; mt<2; mt++){
                    mma16816h(o[mt][2*ep  ], aP[mt],  vh0, vh1);
                    mma16816h(o[mt][2*ep  ], aPl[mt], vh0, vh1);
                    mma16816h(o[mt][2*ep+1], aP[mt],  vh2, vh3);
                    mma16816h(o[mt][2*ep+1], aPl[mt], vh2, vh3);
                }
            }
        }
    }

    // ---- Normalize, split, write ctx hi/lo (bf16 for out-GEMM) ----
    #pragma unroll
    for (int mt=0; mt<2; mt++){
        float i0 = 1.0f/l[mt][0], i1 = 1.0f/l[mt][1];
        size_t row = (size_t)b*SEQ + q0 + wid*32 + mt*16 + g;
        #pragma unroll
        for (int et=0; et<8; et++){
            int n = h*HD + et*8 + 2*t;
            float v00 = o[mt][et][0]*i0, v01 = o[mt][et][1]*i0;
            float v10 = o[mt][et][2]*i1, v11 = o[mt][et][3]*i1;
            bf16 a,bb,c,d;
            splitf(v00,a,bb); splitf(v01,c,d);
            *(uint32_t*)&g_ch[row*DMODEL + n] = pack2(a,c);
            *(uint32_t*)&g_cl[row*DMODEL + n] = pack2(bb,d);
            splitf(v10,a,bb); splitf(v11,c,d);
            *(uint32_t*)&g_ch[(row+8)*DMODEL + n] = pack2(a,c);
            *(uint32_t*)&g_cl[(row+8)*DMODEL + n] = pack2(bb,d);
        }
    }
}

// ============================================================================
extern "C" void kernel_launch(void* const* d_in, const int* in_sizes, int n_in,
                              void* d_out, int out_size)
{
    const float* x  = (const float*)d_in[0];
    const float* Wq = (const float*)d_in[1];
    const float* bq = (const float*)d_in[2];
    const float* Wk = (const float*)d_in[3];
    const float* bk = (const float*)d_in[4];
    const float* Wv = (const float*)d_in[5];
    const float* bv = (const float*)d_in[6];
    const float* Wp = (const float*)d_in[7];
    const float* bp = (const float*)d_in[8];
    float* out = (float*)d_out;

    split_x_kernel<<<((size_t)MR*DMODEL + 255)/256, 256>>>(x);
    prep_all_kernel<<<(NQ*DMODEL + 255)/256, 256>>>(Wq, Wk, Wv, bq, bk, bv, Wp);
    gemm_qkv_kernel<<<dim3(NQ/128, MR/128), 256>>>();

    cudaFuncSetAttribute(attn_mma, cudaFuncAttributeMaxDynamicSharedMemorySize, ATTN_SMEM);
    attn_mma<<<dim3(SEQ/128, BBATCH*NHEAD), 128, ATTN_SMEM>>>();

    gemm_out_kernel<<<dim3(DMODEL/128, MR/128), 256>>>(bp, out);
}

// round 13
// speedup vs baseline: 1.8662x; 1.1856x over previous
#include <cuda_runtime.h>
#include <cuda_bf16.h>
#include <cuda_fp16.h>
#include <math.h>
#include <stdint.h>

#define BBATCH 8
#define SEQ    2048
#define DMODEL 768
#define NHEAD  12
#define HD     64
#define MR     (BBATCH*SEQ)      // 16384
#define NQ     (3*DMODEL)        // 2304

typedef __nv_bfloat16 bf16;

// ---- static device scratch (no allocations allowed) ----
__device__ bf16  g_xh[(size_t)MR*DMODEL],  g_xl[(size_t)MR*DMODEL];
__device__ bf16  g_Wth[(size_t)NQ*DMODEL], g_Wtl[(size_t)NQ*DMODEL];   // [n][k] n-major
__device__ float g_bqkv[NQ];
__device__ bf16  g_Wpth[(size_t)DMODEL*DMODEL], g_Wptl[(size_t)DMODEL*DMODEL]; // [n][k]
__device__ __half g_qh[(size_t)MR*NQ];                                 // QKV fp16 (hi only)
__device__ bf16  g_ch[(size_t)MR*DMODEL],  g_cl[(size_t)MR*DMODEL];    // ctx split (bf16)

__device__ __forceinline__ void splitf(float v, bf16 &h, bf16 &l){
    h = __float2bfloat16(v);
    l = __float2bfloat16(v - __bfloat162float(h));
}
__device__ __forceinline__ uint32_t pack2(bf16 a, bf16 b){
    union { bf16 v[2]; uint32_t u; } t; t.v[0]=a; t.v[1]=b; return t.u;
}
__device__ __forceinline__ uint32_t pack2f16(float a, float b){
    __half2 h2 = __floats2half2_rn(a, b);
    return *(uint32_t*)&h2;
}
__device__ __forceinline__ void mma16816(float c[4], const uint32_t a[4],
                                         uint32_t b0, uint32_t b1){
    asm volatile("mma.sync.aligned.m16n8k16.row.col.f32.bf16.bf16.f32 "
        "{%0,%1,%2,%3},{%4,%5,%6,%7},{%8,%9},{%0,%1,%2,%3};"
        : "+f"(c[0]),"+f"(c[1]),"+f"(c[2]),"+f"(c[3])
        : "r"(a[0]),"r"(a[1]),"r"(a[2]),"r"(a[3]),"r"(b0),"r"(b1));
}
__device__ __forceinline__ void mma16816h(float c[4], const uint32_t a[4],
                                          uint32_t b0, uint32_t b1){
    asm volatile("mma.sync.aligned.m16n8k16.row.col.f32.f16.f16.f32 "
        "{%0,%1,%2,%3},{%4,%5,%6,%7},{%8,%9},{%0,%1,%2,%3};"
        : "+f"(c[0]),"+f"(c[1]),"+f"(c[2]),"+f"(c[3])
        : "r"(a[0]),"r"(a[1]),"r"(a[2]),"r"(a[3]),"r"(b0),"r"(b1));
}
__device__ __forceinline__ uint32_t smem_u32(const void* p){
    uint32_t r;
    asm("{ .reg .u64 t; cvta.to.shared.u64 t, %1; cvt.u32.u64 %0, t; }" : "=r"(r) : "l"(p));
    return r;
}
__device__ __forceinline__ void cp16(uint32_t dst, const void* src){
    asm volatile("cp.async.cg.shared.global [%0], [%1], 16;" :: "r"(dst), "l"(src));
}
#define CP_COMMIT()  asm volatile("cp.async.commit_group;" ::: "memory")
#define CP_WAIT(n)   asm volatile("cp.async.wait_group %0;" :: "n"(n) : "memory")
#define LDSM4(r0,r1,r2,r3,a) \
    asm volatile("ldmatrix.sync.aligned.m8n8.x4.shared.b16 {%0,%1,%2,%3}, [%4];" \
        : "=r"(r0),"=r"(r1),"=r"(r2),"=r"(r3) : "r"(a))
#define LDSM4T(r0,r1,r2,r3,a) \
    asm volatile("ldmatrix.sync.aligned.m8n8.x4.trans.shared.b16 {%0,%1,%2,%3}, [%4];" \
        : "=r"(r0),"=r"(r1),"=r"(r2),"=r"(r3) : "r"(a))

// Fold attention score scale AND log2(e) into Wq/bq so softmax is exp2(s - m).
#define QFOLD (1.4426950408889634f / (8.0f + 1e-6f))

// ============================================================================
// Prep kernels
// ============================================================================
__global__ void split_x_kernel(const float* __restrict__ x){
    size_t i = (size_t)blockIdx.x*blockDim.x + threadIdx.x;
    if (i < (size_t)MR*DMODEL) splitf(x[i], g_xh[i], g_xl[i]);
}

__global__ void prep_all_kernel(const float* __restrict__ Wq, const float* __restrict__ Wk,
                                const float* __restrict__ Wv, const float* __restrict__ bq,
                                const float* __restrict__ bk, const float* __restrict__ bv,
                                const float* __restrict__ Wp){
    int idx = blockIdx.x*blockDim.x + threadIdx.x;
    if (idx < NQ*DMODEL){
        int n = idx / DMODEL, k = idx - n*DMODEL;
        int sec = n / DMODEL;
        int r = n - sec*DMODEL;
        int h = r >> 6, e = r & 63;
        const float* W = (sec==0) ? Wq : (sec==1 ? Wk : Wv);
        float v = W[((size_t)h*DMODEL + k)*HD + e];
        if (sec == 0) v *= QFOLD;
        splitf(v, g_Wth[idx], g_Wtl[idx]);
    }
    if (idx < DMODEL*DMODEL){
        int n = idx / DMODEL, k = idx - n*DMODEL;
        splitf(Wp[(size_t)k*DMODEL + n], g_Wpth[idx], g_Wptl[idx]);
    }
    if (idx < NQ){
        int sec = idx / DMODEL, r = idx - sec*DMODEL;
        const float* bb = (sec==0) ? bq : (sec==1 ? bk : bv);
        float v = bb[r];
        if (sec == 0) v *= QFOLD;
        g_bqkv[idx] = v;
    }
}

// ============================================================================
// Split-bf16 MMA GEMM (R6-measured structure): static smem, register-staged
// prefetch, ldmatrix fragment loads. 128x128 tile, BK=32, 256 threads.
// SPLIT_OUT=true writes fp16 (rn, hi only) for attention; else fp32 to Cf.
// ============================================================================
template<bool SPLIT_OUT>
__device__ __forceinline__ void gemm_core(
    const bf16* __restrict__ Ah, const bf16* __restrict__ Al,
    const bf16* __restrict__ Bth, const bf16* __restrict__ Btl,
    const float* __restrict__ bias, int K, int N,
    __half* __restrict__ Ch, float* __restrict__ Cf)
{
    constexpr int SA = 40;
    __shared__ bf16 As[2][128*SA];
    __shared__ bf16 Bs[2][128*SA];
    const int tid  = threadIdx.x;
    const int lane = tid & 31, wid = tid >> 5;
    const int g = lane >> 2, t = lane & 3;
    const int wm = (wid & 1) * 64, wn = (wid >> 1) * 32;
    const size_t bm0 = (size_t)blockIdx.y * 128;
    const size_t bn0 = (size_t)blockIdx.x * 128;

    const uint32_t aAs0 = smem_u32(As[0]), aAs1 = smem_u32(As[1]);
    const uint32_t aBs0 = smem_u32(Bs[0]), aBs1 = smem_u32(Bs[1]);
    const int offA = (lane & 15)*SA + (lane >> 4)*8;
    const int offB = ((lane & 7) + (lane >> 4)*8)*SA + ((lane >> 3) & 1)*8;

    float acc[4][4][4];
    #pragma unroll
    for (int a=0;a<4;a++)
        #pragma unroll
        for (int b=0;b<4;b++)
            #pragma unroll
            for (int c=0;c<4;c++) acc[a][b][c] = 0.0f;

    const int lr = tid >> 2;
    const int lc = (tid & 3) << 3;
    uint4 pa[2][2], pb[2][2];
    #pragma unroll
    for (int i=0;i<2;i++){
        int r = lr + i*64;
        pa[0][i] = *(const uint4*)&Ah [(bm0 + r)*K + lc];
        pa[1][i] = *(const uint4*)&Al [(bm0 + r)*K + lc];
        pb[0][i] = *(const uint4*)&Bth[(bn0 + r)*K + lc];
        pb[1][i] = *(const uint4*)&Btl[(bn0 + r)*K + lc];
    }

    for (int k0 = 0; k0 < K; k0 += 32){
        __syncthreads();
        #pragma unroll
        for (int i=0;i<2;i++){
            int r = lr + i*64;
            *(uint4*)&As[0][r*SA + lc] = pa[0][i];
            *(uint4*)&As[1][r*SA + lc] = pa[1][i];
            *(uint4*)&Bs[0][r*SA + lc] = pb[0][i];
            *(uint4*)&Bs[1][r*SA + lc] = pb[1][i];
        }
        __syncthreads();
        if (k0 + 32 < K){
            #pragma unroll
            for (int i=0;i<2;i++){
                int r = lr + i*64;
                pa[0][i] = *(const uint4*)&Ah [(bm0 + r)*K + k0+32 + lc];
                pa[1][i] = *(const uint4*)&Al [(bm0 + r)*K + k0+32 + lc];
                pb[0][i] = *(const uint4*)&Bth[(bn0 + r)*K + k0+32 + lc];
                pb[1][i] = *(const uint4*)&Btl[(bn0 + r)*K + k0+32 + lc];
            }
        }
        #pragma unroll
        for (int ks = 0; ks < 32; ks += 16){
            uint32_t afh[4][4], afl[4][4];
            #pragma unroll
            for (int mt=0; mt<4; mt++){
                uint32_t adr = aAs0 + 2*((wm + mt*16)*SA + ks + offA);
                LDSM4(afh[mt][0], afh[mt][1], afh[mt][2], afh[mt][3], adr);
                adr = aAs1 + 2*((wm + mt*16)*SA + ks + offA);
                LDSM4(afl[mt][0], afl[mt][1], afl[mt][2], afl[mt][3], adr);
            }
            uint32_t bh[2][4], bl[2][4];
            #pragma unroll
            for (int np=0; np<2; np++){
                uint32_t adr = aBs0 + 2*((wn + np*16)*SA + ks + offB);
                LDSM4(bh[np][0], bh[np][1], bh[np][2], bh[np][3], adr);
                adr = aBs1 + 2*((wn + np*16)*SA + ks + offB);
                LDSM4(bl[np][0], bl[np][1], bl[np][2], bl[np][3], adr);
            }
            #pragma unroll
            for (int np=0; np<2; np++){
                #pragma unroll
                for (int hf=0; hf<2; hf++){
                    int nt = np*2 + hf;
                    uint32_t bh0 = bh[np][2*hf], bh1 = bh[np][2*hf+1];
                    uint32_t bl0 = bl[np][2*hf], bl1 = bl[np][2*hf+1];
                    #pragma unroll
                    for (int mt=0; mt<4; mt++){
                        mma16816(acc[mt][nt], afh[mt], bh0, bh1);
                        mma16816(acc[mt][nt], afh[mt], bl0, bl1);
                        mma16816(acc[mt][nt], afl[mt], bh0, bh1);
                    }
                }
            }
        }
    }

    #pragma unroll
    for (int mt=0; mt<4; mt++){
        #pragma unroll
        for (int nt=0; nt<4; nt++){
            size_t n = bn0 + wn + nt*8 + 2*t;
            float b0v = bias[n], b1v = bias[n+1];
            size_t m = bm0 + wm + mt*16 + g;
            float v00 = acc[mt][nt][0] + b0v, v01 = acc[mt][nt][1] + b1v;
            float v10 = acc[mt][nt][2] + b0v, v11 = acc[mt][nt][3] + b1v;
            if (SPLIT_OUT){
                *(uint32_t*)&Ch[m*N + n]     = pack2f16(v00, v01);
                *(uint32_t*)&Ch[(m+8)*N + n] = pack2f16(v10, v11);
            } else {
                float2 fa; fa.x = v00; fa.y = v01;
                float2 fb; fb.x = v10; fb.y = v11;
                *(float2*)&Cf[m*N + n]     = fa;
                *(float2*)&Cf[(m+8)*N + n] = fb;
            }
        }
    }
}

__global__ __launch_bounds__(256) void gemm_qkv_kernel(){
    gemm_core<true>(g_xh, g_xl, g_Wth, g_Wtl, g_bqkv, DMODEL, NQ, g_qh, nullptr);
}
__global__ __launch_bounds__(256) void gemm_out_kernel(const float* __restrict__ bp,
                                                       float* __restrict__ out){
    gemm_core<false>(g_ch, g_cl, g_Wpth, g_Wptl, bp, DMODEL, DMODEL, nullptr, out);
}

// ============================================================================
// Flash attention, fp16 1-term: S = Qh*Kh ; O += Ph*Vh.
// 128-q-row blocks, ldmatrix frags, cp.async double-buffered K/V.
// Q pre-scaled by QFOLD -> softmax = exp2(s - m).
// ============================================================================
#define KV_ARR   (64*72)
#define KV_ARRB  (KV_ARR*2)
#define KV_BUFB  (2*KV_ARRB)                 // Kh, Vh
#define ATTN_SMEM (128*72*2 + 2*KV_BUFB)     // 18432 + 36864 = 55296

__global__ __launch_bounds__(128) void attn_mma(){
    extern __shared__ __align__(16) char smraw[];
    __half* Qh = (__half*)smraw;           // [128][72] fp16
    const uint32_t aQh = smem_u32(Qh);
    const uint32_t aKV = aQh + 2*128*72;

    const int tid  = threadIdx.x;
    const int lane = tid & 31, wid = tid >> 5;
    const int g = lane >> 2, t = lane & 3;
    const int b = blockIdx.y / NHEAD, h = blockIdx.y % NHEAD;
    const int q0 = blockIdx.x * 128;
    const size_t rowbase = (size_t)b*SEQ*NQ + (size_t)h*HD;

    #pragma unroll
    for (int i=0;i<8;i++){
        int v = tid + i*128;
        int r = v >> 3, c = (v & 7) << 3;
        *(uint4*)&Qh[r*72 + c] = *(const uint4*)&g_qh[rowbase + (size_t)(q0+r)*NQ + c];
    }

    auto issue_kv = [&](int it, int bufIdx){
        uint32_t base = aKV + bufIdx*KV_BUFB;
        #pragma unroll
        for (int i=0;i<4;i++){
            int v = tid + i*128;
            int r = v >> 3, c = (v & 7) << 3;
            size_t grow = rowbase + (size_t)(it*64 + r)*NQ;
            uint32_t doff = 2*(r*72 + c);
            cp16(base + 0*KV_ARRB + doff, &g_qh[grow +   DMODEL + c]);   // Kh
            cp16(base + 1*KV_ARRB + doff, &g_qh[grow + 2*DMODEL + c]);   // Vh
        }
        CP_COMMIT();
    };

    const int offA = (lane & 15)*72 + (lane >> 4)*8;
    const int offB = ((lane & 7) + (lane >> 4)*8)*72 + ((lane >> 3) & 1)*8;
    const int offV = ((lane & 7) + ((lane >> 3) & 1)*8)*72 + (lane >> 4)*8;

    float m[2][2], l[2][2], o[2][8][4];
    #pragma unroll
    for (int mt=0;mt<2;mt++){
        m[mt][0]=-1e30f; m[mt][1]=-1e30f; l[mt][0]=0.0f; l[mt][1]=0.0f;
        #pragma unroll
        for (int e=0;e<8;e++){ o[mt][e][0]=0; o[mt][e][1]=0; o[mt][e][2]=0; o[mt][e][3]=0; }
    }
    const int NT = SEQ/64;

    issue_kv(0, 0);

    for (int it = 0; it < NT; it++){
        const int buf = it & 1;
        __syncthreads();
        if (it + 1 < NT){ issue_kv(it + 1, buf ^ 1); CP_WAIT(1); }
        else            { CP_WAIT(0); }
        __syncthreads();

        const uint32_t aKh = aKV + buf*KV_BUFB;
        const uint32_t aVh = aKh + KV_ARRB;

        // ---- S = Q K^T (fp16 1-term), 2 m-tiles per warp ----
        float s[2][8][4];
        #pragma unroll
        for (int mt=0;mt<2;mt++)
            #pragma unroll
            for (int nt=0;nt<8;nt++){ s[mt][nt][0]=0; s[mt][nt][1]=0; s[mt][nt][2]=0; s[mt][nt][3]=0; }

        #pragma unroll
        for (int ks=0; ks<64; ks+=16){
            uint32_t ah[2][4];
            #pragma unroll
            for (int mt=0; mt<2; mt++){
                uint32_t adr = aQh + 2*((wid*32 + mt*16)*72 + ks + offA);
                LDSM4(ah[mt][0], ah[mt][1], ah[mt][2], ah[mt][3], adr);
            }
            #pragma unroll
            for (int np=0; np<4; np++){
                uint32_t kh0,kh1,kh2,kh3;
                uint32_t adr = aKh + 2*((np*16)*72 + ks + offB);
                LDSM4(kh0,kh1,kh2,kh3, adr);
                #pragma unroll
                for (int mt=0; mt<2; mt++){
                    mma16816h(s[mt][2*np  ], ah[mt], kh0, kh1);
                    mma16816h(s[mt][2*np+1], ah[mt], kh2, kh3);
                }
            }
        }

        // ---- Online softmax per m-tile (base-2 domain, scores pre-scaled) ----
        uint32_t ph01[2][8], ph23[2][8];
        #pragma unroll
        for (int mt=0; mt<2; mt++){
            float rm0 = -1e30f, rm1 = -1e30f;
            #pragma unroll
            for (int nt=0;nt<8;nt++){
                rm0 = fmaxf(rm0, fmaxf(s[mt][nt][0], s[mt][nt][1]));
                rm1 = fmaxf(rm1, fmaxf(s[mt][nt][2], s[mt][nt][3]));
            }
            rm0 = fmaxf(rm0, __shfl_xor_sync(0xffffffffu, rm0, 1));
            rm0 = fmaxf(rm0, __shfl_xor_sync(0xffffffffu, rm0, 2));
            rm1 = fmaxf(rm1, __shfl_xor_sync(0xffffffffu, rm1, 1));
            rm1 = fmaxf(rm1, __shfl_xor_sync(0xffffffffu, rm1, 2));
            float mn0 = fmaxf(m[mt][0], rm0), mn1 = fmaxf(m[mt][1], rm1);
            float cr0 = exp2f(m[mt][0] - mn0), cr1 = exp2f(m[mt][1] - mn1);
            m[mt][0] = mn0; m[mt][1] = mn1;

            float rs0 = 0.0f, rs1 = 0.0f;
            #pragma unroll
            for (int nt=0;nt<8;nt++){
                float p0 = exp2f(s[mt][nt][0]-mn0), p1 = exp2f(s[mt][nt][1]-mn0);
                float p2 = exp2f(s[mt][nt][2]-mn1), p3 = exp2f(s[mt][nt][3]-mn1);
                rs0 += p0+p1; rs1 += p2+p3;
                ph01[mt][nt] = pack2f16(p0, p1);
                ph23[mt][nt] = pack2f16(p2, p3);
            }
            rs0 += __shfl_xor_sync(0xffffffffu, rs0, 1);
            rs0 += __shfl_xor_sync(0xffffffffu, rs0, 2);
            rs1 += __shfl_xor_sync(0xffffffffu, rs1, 1);
            rs1 += __shfl_xor_sync(0xffffffffu, rs1, 2);
            l[mt][0] = l[mt][0]*cr0 + rs0; l[mt][1] = l[mt][1]*cr1 + rs1;
            #pragma unroll
            for (int e=0;e<8;e++){
                o[mt][e][0]*=cr0; o[mt][e][1]*=cr0; o[mt][e][2]*=cr1; o[mt][e][3]*=cr1;
            }
        }

        // ---- O += P @ V (fp16 1-term) ----
        #pragma unroll
        for (int j2=0; j2<4; j2++){
            uint32_t aP[2][4];
            #pragma unroll
            for (int mt=0; mt<2; mt++){
                aP[mt][0]=ph01[mt][2*j2];   aP[mt][1]=ph23[mt][2*j2];
                aP[mt][2]=ph01[mt][2*j2+1]; aP[mt][3]=ph23[mt][2*j2+1];
            }
            #pragma unroll
            for (int ep=0; ep<4; ep++){
                uint32_t vh0,vh1,vh2,vh3;
                uint32_t adr = aVh + 2*((j2*16)*72 + ep*16 + offV);
                LDSM4T(vh0,vh1,vh2,vh3, adr);
                #pragma unroll
                for (int mt=0; mt<2; mt++){
                    mma16816h(o[mt][2*ep  ], aP[mt], vh0, vh1);
                    mma16816h(o[mt][2*ep+1], aP[mt], vh2, vh3);
                }
            }
        }
    }

    // ---- Normalize, split, write ctx hi/lo (bf16 for out-GEMM) ----
    #pragma unroll
    for (int mt=0; mt<2; mt++){
        float i0 = 1.0f/l[mt][0], i1 = 1.0f/l[mt][1];
        size_t row = (size_t)b*SEQ + q0 + wid*32 + mt*16 + g;
        #pragma unroll
        for (int et=0; et<8; et++){
            int n = h*HD + et*8 + 2*t;
            float v00 = o[mt][et][0]*i0, v01 = o[mt][et][1]*i0;
            float v10 = o[mt][et][2]*i1, v11 = o[mt][et][3]*i1;
            bf16 a,bb,c,d;
            splitf(v00,a,bb); splitf(v01,c,d);
            *(uint32_t*)&g_ch[row*DMODEL + n] = pack2(a,c);
            *(uint32_t*)&g_cl[row*DMODEL + n] = pack2(bb,d);
            splitf(v10,a,bb); splitf(v11,c,d);
            *(uint32_t*)&g_ch[(row+8)*DMODEL + n] = pack2(a,c);
            *(uint32_t*)&g_cl[(row+8)*DMODEL + n] = pack2(bb,d);
        }
    }
}

// ============================================================================
extern "C" void kernel_launch(void* const* d_in, const int* in_sizes, int n_in,
                              void* d_out, int out_size)
{
    const float* x  = (const float*)d_in[0];
    const float* Wq = (const float*)d_in[1];
    const float* bq = (const float*)d_in[2];
    const float* Wk = (const float*)d_in[3];
    const float* bk = (const float*)d_in[4];
    const float* Wv = (const float*)d_in[5];
    const float* bv = (const float*)d_in[6];
    const float* Wp = (const float*)d_in[7];
    const float* bp = (const float*)d_in[8];
    float* out = (float*)d_out;

    split_x_kernel<<<((size_t)MR*DMODEL + 255)/256, 256>>>(x);
    prep_all_kernel<<<(NQ*DMODEL + 255)/256, 256>>>(Wq, Wk, Wv, bq, bk, bv, Wp);
    gemm_qkv_kernel<<<dim3(NQ/128, MR/128), 256>>>();

    cudaFuncSetAttribute(attn_mma, cudaFuncAttributeMaxDynamicSharedMemorySize, ATTN_SMEM);
    attn_mma<<<dim3(SEQ/128, BBATCH*NHEAD), 128, ATTN_SMEM>>>();

    gemm_out_kernel<<<dim3(DMODEL/128, MR/128), 256>>>(bp, out);
}

// round 14
// speedup vs baseline: 2.2749x; 1.2190x over previous
#include <cuda_runtime.h>
#include <cuda_bf16.h>
#include <cuda_fp16.h>
#include <math.h>
#include <stdint.h>

#define BBATCH 8
#define SEQ    2048
#define DMODEL 768
#define NHEAD  12
#define HD     64
#define MR     (BBATCH*SEQ)      // 16384
#define NQ     (3*DMODEL)        // 2304

typedef __half f16;

// ---- static device scratch (no allocations allowed) ----
__device__ f16   g_xh[(size_t)MR*DMODEL],  g_xl[(size_t)MR*DMODEL];  // x fp16 hi/lo
__device__ f16   g_Wt[(size_t)NQ*DMODEL];                            // [n][k] fp16
__device__ float g_bqkv[NQ];
__device__ f16   g_Wpt[(size_t)DMODEL*DMODEL];                       // [n][k] fp16
__device__ f16   g_qh[(size_t)MR*NQ];                                // QKV fp16
__device__ f16   g_ch[(size_t)MR*DMODEL], g_cl[(size_t)MR*DMODEL];   // ctx fp16 hi/lo

__device__ __forceinline__ void splith(float v, f16 &h, f16 &l){
    h = __float2half_rn(v);
    l = __float2half_rn(v - __half2float(h));
}
__device__ __forceinline__ uint32_t pack2h(f16 a, f16 b){
    union { f16 v[2]; uint32_t u; } t; t.v[0]=a; t.v[1]=b; return t.u;
}
__device__ __forceinline__ uint32_t pack2f16(float a, float b){
    __half2 h2 = __floats2half2_rn(a, b);
    return *(uint32_t*)&h2;
}
__device__ __forceinline__ void mma16816h(float c[4], const uint32_t a[4],
                                          uint32_t b0, uint32_t b1){
    asm volatile("mma.sync.aligned.m16n8k16.row.col.f32.f16.f16.f32 "
        "{%0,%1,%2,%3},{%4,%5,%6,%7},{%8,%9},{%0,%1,%2,%3};"
        : "+f"(c[0]),"+f"(c[1]),"+f"(c[2]),"+f"(c[3])
        : "r"(a[0]),"r"(a[1]),"r"(a[2]),"r"(a[3]),"r"(b0),"r"(b1));
}
__device__ __forceinline__ uint32_t smem_u32(const void* p){
    uint32_t r;
    asm("{ .reg .u64 t; cvta.to.shared.u64 t, %1; cvt.u32.u64 %0, t; }" : "=r"(r) : "l"(p));
    return r;
}
__device__ __forceinline__ void cp16(uint32_t dst, const void* src){
    asm volatile("cp.async.cg.shared.global [%0], [%1], 16;" :: "r"(dst), "l"(src));
}
#define CP_COMMIT()  asm volatile("cp.async.commit_group;" ::: "memory")
#define CP_WAIT(n)   asm volatile("cp.async.wait_group %0;" :: "n"(n) : "memory")
#define LDSM4(r0,r1,r2,r3,a) \
    asm volatile("ldmatrix.sync.aligned.m8n8.x4.shared.b16 {%0,%1,%2,%3}, [%4];" \
        : "=r"(r0),"=r"(r1),"=r"(r2),"=r"(r3) : "r"(a))
#define LDSM4T(r0,r1,r2,r3,a) \
    asm volatile("ldmatrix.sync.aligned.m8n8.x4.trans.shared.b16 {%0,%1,%2,%3}, [%4];" \
        : "=r"(r0),"=r"(r1),"=r"(r2),"=r"(r3) : "r"(a))

// Fold attention score scale AND log2(e) into Wq/bq so softmax is exp2(s - m).
#define QFOLD (1.4426950408889634f / (8.0f + 1e-6f))

// ============================================================================
// Prep kernels
// ============================================================================
__global__ void split_x_kernel(const float* __restrict__ x){
    size_t i = (size_t)blockIdx.x*blockDim.x + threadIdx.x;
    if (i < (size_t)MR*DMODEL) splith(x[i], g_xh[i], g_xl[i]);
}

__global__ void prep_all_kernel(const float* __restrict__ Wq, const float* __restrict__ Wk,
                                const float* __restrict__ Wv, const float* __restrict__ bq,
                                const float* __restrict__ bk, const float* __restrict__ bv,
                                const float* __restrict__ Wp){
    int idx = blockIdx.x*blockDim.x + threadIdx.x;
    if (idx < NQ*DMODEL){
        int n = idx / DMODEL, k = idx - n*DMODEL;
        int sec = n / DMODEL;
        int r = n - sec*DMODEL;
        int h = r >> 6, e = r & 63;
        const float* W = (sec==0) ? Wq : (sec==1 ? Wk : Wv);
        float v = W[((size_t)h*DMODEL + k)*HD + e];
        if (sec == 0) v *= QFOLD;
        g_Wt[idx] = __float2half_rn(v);
    }
    if (idx < DMODEL*DMODEL){
        int n = idx / DMODEL, k = idx - n*DMODEL;
        g_Wpt[idx] = __float2half_rn(Wp[(size_t)k*DMODEL + n]);
    }
    if (idx < NQ){
        int sec = idx / DMODEL, r = idx - sec*DMODEL;
        const float* bb = (sec==0) ? bq : (sec==1 ? bk : bv);
        float v = bb[r];
        if (sec == 0) v *= QFOLD;
        g_bqkv[idx] = v;
    }
}

// ============================================================================
// fp16 2-term MMA GEMM: C = (Ah+Al) @ Bt^T + bias  (B fp16 single).
// R6-measured structure: static smem, register-staged prefetch, ldmatrix.
// 128x128 tile, BK=32, 256 threads (8 warps, 2m x 4n), warp tile 64x32.
// ============================================================================
template<bool SPLIT_OUT>
__device__ __forceinline__ void gemm_core(
    const f16* __restrict__ Ah, const f16* __restrict__ Al,
    const f16* __restrict__ Bt,
    const float* __restrict__ bias, int K, int N,
    f16* __restrict__ Ch, f16* __restrict__ Cl, float* __restrict__ Cf)
{
    constexpr int SA = 40;
    __shared__ f16 AsH[128*SA];
    __shared__ f16 AsL[128*SA];
    __shared__ f16 Bs [128*SA];
    const int tid  = threadIdx.x;
    const int lane = tid & 31, wid = tid >> 5;
    const int g = lane >> 2, t = lane & 3;
    const int wm = (wid & 1) * 64, wn = (wid >> 1) * 32;
    const size_t bm0 = (size_t)blockIdx.y * 128;
    const size_t bn0 = (size_t)blockIdx.x * 128;

    const uint32_t aAsH = smem_u32(AsH), aAsL = smem_u32(AsL);
    const uint32_t aBs  = smem_u32(Bs);
    const int offA = (lane & 15)*SA + (lane >> 4)*8;
    const int offB = ((lane & 7) + (lane >> 4)*8)*SA + ((lane >> 3) & 1)*8;

    float acc[4][4][4];
    #pragma unroll
    for (int a=0;a<4;a++)
        #pragma unroll
        for (int b=0;b<4;b++)
            #pragma unroll
            for (int c=0;c<4;c++) acc[a][b][c] = 0.0f;

    const int lr = tid >> 2;
    const int lc = (tid & 3) << 3;
    uint4 pa[2][2], pb[2];
    #pragma unroll
    for (int i=0;i<2;i++){
        int r = lr + i*64;
        pa[0][i] = *(const uint4*)&Ah[(bm0 + r)*K + lc];
        pa[1][i] = *(const uint4*)&Al[(bm0 + r)*K + lc];
        pb[i]    = *(const uint4*)&Bt[(bn0 + r)*K + lc];
    }

    for (int k0 = 0; k0 < K; k0 += 32){
        __syncthreads();
        #pragma unroll
        for (int i=0;i<2;i++){
            int r = lr + i*64;
            *(uint4*)&AsH[r*SA + lc] = pa[0][i];
            *(uint4*)&AsL[r*SA + lc] = pa[1][i];
            *(uint4*)&Bs [r*SA + lc] = pb[i];
        }
        __syncthreads();
        if (k0 + 32 < K){
            #pragma unroll
            for (int i=0;i<2;i++){
                int r = lr + i*64;
                pa[0][i] = *(const uint4*)&Ah[(bm0 + r)*K + k0+32 + lc];
                pa[1][i] = *(const uint4*)&Al[(bm0 + r)*K + k0+32 + lc];
                pb[i]    = *(const uint4*)&Bt[(bn0 + r)*K + k0+32 + lc];
            }
        }
        #pragma unroll
        for (int ks = 0; ks < 32; ks += 16){
            uint32_t afh[4][4], afl[4][4];
            #pragma unroll
            for (int mt=0; mt<4; mt++){
                uint32_t adr = aAsH + 2*((wm + mt*16)*SA + ks + offA);
                LDSM4(afh[mt][0], afh[mt][1], afh[mt][2], afh[mt][3], adr);
                adr = aAsL + 2*((wm + mt*16)*SA + ks + offA);
                LDSM4(afl[mt][0], afl[mt][1], afl[mt][2], afl[mt][3], adr);
            }
            uint32_t bh[2][4];
            #pragma unroll
            for (int np=0; np<2; np++){
                uint32_t adr = aBs + 2*((wn + np*16)*SA + ks + offB);
                LDSM4(bh[np][0], bh[np][1], bh[np][2], bh[np][3], adr);
            }
            #pragma unroll
            for (int np=0; np<2; np++){
                #pragma unroll
                for (int hf=0; hf<2; hf++){
                    int nt = np*2 + hf;
                    uint32_t b0 = bh[np][2*hf], b1 = bh[np][2*hf+1];
                    #pragma unroll
                    for (int mt=0; mt<4; mt++){
                        mma16816h(acc[mt][nt], afh[mt], b0, b1);
                        mma16816h(acc[mt][nt], afl[mt], b0, b1);
                    }
                }
            }
        }
    }

    #pragma unroll
    for (int mt=0; mt<4; mt++){
        #pragma unroll
        for (int nt=0; nt<4; nt++){
            size_t n = bn0 + wn + nt*8 + 2*t;
            float b0v = bias[n], b1v = bias[n+1];
            size_t m = bm0 + wm + mt*16 + g;
            float v00 = acc[mt][nt][0] + b0v, v01 = acc[mt][nt][1] + b1v;
            float v10 = acc[mt][nt][2] + b0v, v11 = acc[mt][nt][3] + b1v;
            if (SPLIT_OUT){
                *(uint32_t*)&Ch[m*N + n]     = pack2f16(v00, v01);
                *(uint32_t*)&Ch[(m+8)*N + n] = pack2f16(v10, v11);
            } else {
                float2 fa; fa.x = v00; fa.y = v01;
                float2 fb; fb.x = v10; fb.y = v11;
                *(float2*)&Cf[m*N + n]     = fa;
                *(float2*)&Cf[(m+8)*N + n] = fb;
            }
            (void)Cl;
        }
    }
}

__global__ __launch_bounds__(256) void gemm_qkv_kernel(){
    gemm_core<true>(g_xh, g_xl, g_Wt, g_bqkv, DMODEL, NQ, g_qh, nullptr, nullptr);
}
__global__ __launch_bounds__(256) void gemm_out_kernel(const float* __restrict__ bp,
                                                       float* __restrict__ out){
    gemm_core<false>(g_ch, g_cl, g_Wpt, bp, DMODEL, DMODEL, nullptr, nullptr, out);
}

// ============================================================================
// Flash attention, fp16 1-term: S = Qh*Kh ; O += Ph*Vh.
// 128-q-row blocks, ldmatrix frags, cp.async double-buffered K/V.
// Q pre-scaled by QFOLD -> softmax = exp2(s - m).
// ============================================================================
#define KV_ARR   (64*72)
#define KV_ARRB  (KV_ARR*2)
#define KV_BUFB  (2*KV_ARRB)                 // Kh, Vh
#define ATTN_SMEM (128*72*2 + 2*KV_BUFB)     // 55296

__global__ __launch_bounds__(128, 3) void attn_mma(){
    extern __shared__ __align__(16) char smraw[];
    f16* Qh = (f16*)smraw;                 // [128][72] fp16
    const uint32_t aQh = smem_u32(Qh);
    const uint32_t aKV = aQh + 2*128*72;

    const int tid  = threadIdx.x;
    const int lane = tid & 31, wid = tid >> 5;
    const int g = lane >> 2, t = lane & 3;
    const int b = blockIdx.y / NHEAD, h = blockIdx.y % NHEAD;
    const int q0 = blockIdx.x * 128;
    const size_t rowbase = (size_t)b*SEQ*NQ + (size_t)h*HD;

    #pragma unroll
    for (int i=0;i<8;i++){
        int v = tid + i*128;
        int r = v >> 3, c = (v & 7) << 3;
        *(uint4*)&Qh[r*72 + c] = *(const uint4*)&g_qh[rowbase + (size_t)(q0+r)*NQ + c];
    }

    auto issue_kv = [&](int it, int bufIdx){
        uint32_t base = aKV + bufIdx*KV_BUFB;
        #pragma unroll
        for (int i=0;i<4;i++){
            int v = tid + i*128;
            int r = v >> 3, c = (v & 7) << 3;
            size_t grow = rowbase + (size_t)(it*64 + r)*NQ;
            uint32_t doff = 2*(r*72 + c);
            cp16(base + 0*KV_ARRB + doff, &g_qh[grow +   DMODEL + c]);   // Kh
            cp16(base + 1*KV_ARRB + doff, &g_qh[grow + 2*DMODEL + c]);   // Vh
        }
        CP_COMMIT();
    };

    const int offA = (lane & 15)*72 + (lane >> 4)*8;
    const int offB = ((lane & 7) + (lane >> 4)*8)*72 + ((lane >> 3) & 1)*8;
    const int offV = ((lane & 7) + ((lane >> 3) & 1)*8)*72 + (lane >> 4)*8;

    float m[2][2], l[2][2], o[2][8][4];
    #pragma unroll
    for (int mt=0;mt<2;mt++){
        m[mt][0]=-1e30f; m[mt][1]=-1e30f; l[mt][0]=0.0f; l[mt][1]=0.0f;
        #pragma unroll
        for (int e=0;e<8;e++){ o[mt][e][0]=0; o[mt][e][1]=0; o[mt][e][2]=0; o[mt][e][3]=0; }
    }
    const int NT = SEQ/64;

    issue_kv(0, 0);

    for (int it = 0; it < NT; it++){
        const int buf = it & 1;
        __syncthreads();
        if (it + 1 < NT){ issue_kv(it + 1, buf ^ 1); CP_WAIT(1); }
        else            { CP_WAIT(0); }
        __syncthreads();

        const uint32_t aKh = aKV + buf*KV_BUFB;
        const uint32_t aVh = aKh + KV_ARRB;

        // ---- S = Q K^T (fp16 1-term), 2 m-tiles per warp ----
        float s[2][8][4];
        #pragma unroll
        for (int mt=0;mt<2;mt++)
            #pragma unroll
            for (int nt=0;nt<8;nt++){ s[mt][nt][0]=0; s[mt][nt][1]=0; s[mt][nt][2]=0; s[mt][nt][3]=0; }

        #pragma unroll
        for (int ks=0; ks<64; ks+=16){
            uint32_t ah[2][4];
            #pragma unroll
            for (int mt=0; mt<2; mt++){
                uint32_t adr = aQh + 2*((wid*32 + mt*16)*72 + ks + offA);
                LDSM4(ah[mt][0], ah[mt][1], ah[mt][2], ah[mt][3], adr);
            }
            #pragma unroll
            for (int np=0; np<4; np++){
                uint32_t kh0,kh1,kh2,kh3;
                uint32_t adr = aKh + 2*((np*16)*72 + ks + offB);
                LDSM4(kh0,kh1,kh2,kh3, adr);
                #pragma unroll
                for (int mt=0; mt<2; mt++){
                    mma16816h(s[mt][2*np  ], ah[mt], kh0, kh1);
                    mma16816h(s[mt][2*np+1], ah[mt], kh2, kh3);
                }
            }
        }

        // ---- Online softmax per m-tile (base-2 domain, scores pre-scaled) ----
        uint32_t ph01[2][8], ph23[2][8];
        #pragma unroll
        for (int mt=0; mt<2; mt++){
            float rm0 = -1e30f, rm1 = -1e30f;
            #pragma unroll
            for (int nt=0;nt<8;nt++){
                rm0 = fmaxf(rm0, fmaxf(s[mt][nt][0], s[mt][nt][1]));
                rm1 = fmaxf(rm1, fmaxf(s[mt][nt][2], s[mt][nt][3]));
            }
            rm0 = fmaxf(rm0, __shfl_xor_sync(0xffffffffu, rm0, 1));
            rm0 = fmaxf(rm0, __shfl_xor_sync(0xffffffffu, rm0, 2));
            rm1 = fmaxf(rm1, __shfl_xor_sync(0xffffffffu, rm1, 1));
            rm1 = fmaxf(rm1, __shfl_xor_sync(0xffffffffu, rm1, 2));
            float mn0 = fmaxf(m[mt][0], rm0), mn1 = fmaxf(m[mt][1], rm1);
            float cr0 = exp2f(m[mt][0] - mn0), cr1 = exp2f(m[mt][1] - mn1);
            m[mt][0] = mn0; m[mt][1] = mn1;

            float rs0 = 0.0f, rs1 = 0.0f;
            #pragma unroll
            for (int nt=0;nt<8;nt++){
                float p0 = exp2f(s[mt][nt][0]-mn0), p1 = exp2f(s[mt][nt][1]-mn0);
                float p2 = exp2f(s[mt][nt][2]-mn1), p3 = exp2f(s[mt][nt][3]-mn1);
                rs0 += p0+p1; rs1 += p2+p3;
                ph01[mt][nt] = pack2f16(p0, p1);
                ph23[mt][nt] = pack2f16(p2, p3);
            }
            rs0 += __shfl_xor_sync(0xffffffffu, rs0, 1);
            rs0 += __shfl_xor_sync(0xffffffffu, rs0, 2);
            rs1 += __shfl_xor_sync(0xffffffffu, rs1, 1);
            rs1 += __shfl_xor_sync(0xffffffffu, rs1, 2);
            l[mt][0] = l[mt][0]*cr0 + rs0; l[mt][1] = l[mt][1]*cr1 + rs1;
            #pragma unroll
            for (int e=0;e<8;e++){
                o[mt][e][0]*=cr0; o[mt][e][1]*=cr0; o[mt][e][2]*=cr1; o[mt][e][3]*=cr1;
            }
        }

        // ---- O += P @ V (fp16 1-term) ----
        #pragma unroll
        for (int j2=0; j2<4; j2++){
            uint32_t aP[2][4];
            #pragma unroll
            for (int mt=0; mt<2; mt++){
                aP[mt][0]=ph01[mt][2*j2];   aP[mt][1]=ph23[mt][2*j2];
                aP[mt][2]=ph01[mt][2*j2+1]; aP[mt][3]=ph23[mt][2*j2+1];
            }
            #pragma unroll
            for (int ep=0; ep<4; ep++){
                uint32_t vh0,vh1,vh2,vh3;
                uint32_t adr = aVh + 2*((j2*16)*72 + ep*16 + offV);
                LDSM4T(vh0,vh1,vh2,vh3, adr);
                #pragma unroll
                for (int mt=0; mt<2; mt++){
                    mma16816h(o[mt][2*ep  ], aP[mt], vh0, vh1);
                    mma16816h(o[mt][2*ep+1], aP[mt], vh2, vh3);
                }
            }
        }
    }

    // ---- Normalize, split, write ctx hi/lo (fp16 for out-GEMM) ----
    #pragma unroll
    for (int mt=0; mt<2; mt++){
        float i0 = 1.0f/l[mt][0], i1 = 1.0f/l[mt][1];
        size_t row = (size_t)b*SEQ + q0 + wid*32 + mt*16 + g;
        #pragma unroll
        for (int et=0; et<8; et++){
            int n = h*HD + et*8 + 2*t;
            float v00 = o[mt][et][0]*i0, v01 = o[mt][et][1]*i0;
            float v10 = o[mt][et][2]*i1, v11 = o[mt][et][3]*i1;
            f16 a,bb,c,d;
            splith(v00,a,bb); splith(v01,c,d);
            *(uint32_t*)&g_ch[row*DMODEL + n] = pack2h(a,c);
            *(uint32_t*)&g_cl[row*DMODEL + n] = pack2h(bb,d);
            splith(v10,a,bb); splith(v11,c,d);
            *(uint32_t*)&g_ch[(row+8)*DMODEL + n] = pack2h(a,c);
            *(uint32_t*)&g_cl[(row+8)*DMODEL + n] = pack2h(bb,d);
        }
    }
}

// ============================================================================
extern "C" void kernel_launch(void* const* d_in, const int* in_sizes, int n_in,
                              void* d_out, int out_size)
{
    const float* x  = (const float*)d_in[0];
    const float* Wq = (const float*)d_in[1];
    const float* bq = (const float*)d_in[2];
    const float* Wk = (const float*)d_in[3];
    const float* bk = (const float*)d_in[4];
    const float* Wv = (const float*)d_in[5];
    const float* bv = (const float*)d_in[6];
    const float* Wp = (const float*)d_in[7];
    const float* bp = (const float*)d_in[8];
    float* out = (float*)d_out;

    split_x_kernel<<<((size_t)MR*DMODEL + 255)/256, 256>>>(x);
    prep_all_kernel<<<(NQ*DMODEL + 255)/256, 256>>>(Wq, Wk, Wv, bq, bk, bv, Wp);
    gemm_qkv_kernel<<<dim3(NQ/128, MR/128), 256>>>();

    cudaFuncSetAttribute(attn_mma, cudaFuncAttributeMaxDynamicSharedMemorySize, ATTN_SMEM);
    attn_mma<<<dim3(SEQ/128, BBATCH*NHEAD), 128, ATTN_SMEM>>>();

    gemm_out_kernel<<<dim3(DMODEL/128, MR/128), 256>>>(bp, out);
}

// round 15
// speedup vs baseline: 3.3409x; 1.4686x over previous
#include <cuda_runtime.h>
#include <cuda_bf16.h>
#include <cuda_fp16.h>
#include <math.h>
#include <stdint.h>

#define BBATCH 8
#define SEQ    2048
#define DMODEL 768
#define NHEAD  12
#define HD     64
#define MR     (BBATCH*SEQ)      // 16384
#define NQ     (3*DMODEL)        // 2304

typedef __half f16;

// ---- static device scratch (no allocations allowed) ----
__device__ f16   g_x16[(size_t)MR*DMODEL];                           // x fp16
__device__ f16   g_Wt[(size_t)NQ*DMODEL];                            // [n][k] fp16
__device__ float g_bqkv[NQ];
__device__ f16   g_Wpt[(size_t)DMODEL*DMODEL];                       // [n][k] fp16
__device__ f16   g_qh[(size_t)MR*NQ];                                // QKV fp16
__device__ f16   g_ch[(size_t)MR*DMODEL];                            // ctx fp16

__device__ __forceinline__ uint32_t pack2f16(float a, float b){
    __half2 h2 = __floats2half2_rn(a, b);
    return *(uint32_t*)&h2;
}
__device__ __forceinline__ void mma16816h(float c[4], const uint32_t a[4],
                                          uint32_t b0, uint32_t b1){
    asm volatile("mma.sync.aligned.m16n8k16.row.col.f32.f16.f16.f32 "
        "{%0,%1,%2,%3},{%4,%5,%6,%7},{%8,%9},{%0,%1,%2,%3};"
        : "+f"(c[0]),"+f"(c[1]),"+f"(c[2]),"+f"(c[3])
        : "r"(a[0]),"r"(a[1]),"r"(a[2]),"r"(a[3]),"r"(b0),"r"(b1));
}
__device__ __forceinline__ uint32_t smem_u32(const void* p){
    uint32_t r;
    asm("{ .reg .u64 t; cvta.to.shared.u64 t, %1; cvt.u32.u64 %0, t; }" : "=r"(r) : "l"(p));
    return r;
}
__device__ __forceinline__ void cp16(uint32_t dst, const void* src){
    asm volatile("cp.async.cg.shared.global [%0], [%1], 16;" :: "r"(dst), "l"(src));
}
#define CP_COMMIT()  asm volatile("cp.async.commit_group;" ::: "memory")
#define CP_WAIT(n)   asm volatile("cp.async.wait_group %0;" :: "n"(n) : "memory")
#define LDSM4(r0,r1,r2,r3,a) \
    asm volatile("ldmatrix.sync.aligned.m8n8.x4.shared.b16 {%0,%1,%2,%3}, [%4];" \
        : "=r"(r0),"=r"(r1),"=r"(r2),"=r"(r3) : "r"(a))
#define LDSM4T(r0,r1,r2,r3,a) \
    asm volatile("ldmatrix.sync.aligned.m8n8.x4.trans.shared.b16 {%0,%1,%2,%3}, [%4];" \
        : "=r"(r0),"=r"(r1),"=r"(r2),"=r"(r3) : "r"(a))

// Fold attention score scale AND log2(e) into Wq/bq so softmax is exp2(s - m).
#define QFOLD (1.4426950408889634f / (8.0f + 1e-6f))

// ============================================================================
// Prep kernels
// ============================================================================
__global__ void cvt_x_kernel(const float* __restrict__ x){
    size_t i = (size_t)blockIdx.x*blockDim.x + threadIdx.x;
    if (i < (size_t)MR*DMODEL) g_x16[i] = __float2half_rn(x[i]);
}

__global__ void prep_all_kernel(const float* __restrict__ Wq, const float* __restrict__ Wk,
                                const float* __restrict__ Wv, const float* __restrict__ bq,
                                const float* __restrict__ bk, const float* __restrict__ bv,
                                const float* __restrict__ Wp){
    int idx = blockIdx.x*blockDim.x + threadIdx.x;
    if (idx < NQ*DMODEL){
        int n = idx / DMODEL, k = idx - n*DMODEL;
        int sec = n / DMODEL;
        int r = n - sec*DMODEL;
        int h = r >> 6, e = r & 63;
        const float* W = (sec==0) ? Wq : (sec==1 ? Wk : Wv);
        float v = W[((size_t)h*DMODEL + k)*HD + e];
        if (sec == 0) v *= QFOLD;
        g_Wt[idx] = __float2half_rn(v);
    }
    if (idx < DMODEL*DMODEL){
        int n = idx / DMODEL, k = idx - n*DMODEL;
        g_Wpt[idx] = __float2half_rn(Wp[(size_t)k*DMODEL + n]);
    }
    if (idx < NQ){
        int sec = idx / DMODEL, r = idx - sec*DMODEL;
        const float* bb = (sec==0) ? bq : (sec==1 ? bk : bv);
        float v = bb[r];
        if (sec == 0) v *= QFOLD;
        g_bqkv[idx] = v;
    }
}

// ============================================================================
// fp16 1-term MMA GEMM: C = A @ Bt^T + bias.
// R6-measured structure: static smem, register-staged prefetch, ldmatrix.
// 128x128 tile, BK=32, 256 threads (8 warps, 2m x 4n), warp tile 64x32.
// ============================================================================
template<bool F16_OUT>
__device__ __forceinline__ void gemm_core(
    const f16* __restrict__ A, const f16* __restrict__ Bt,
    const float* __restrict__ bias, int K, int N,
    f16* __restrict__ Ch, float* __restrict__ Cf)
{
    constexpr int SA = 40;
    __shared__ f16 As[128*SA];
    __shared__ f16 Bs[128*SA];
    const int tid  = threadIdx.x;
    const int lane = tid & 31, wid = tid >> 5;
    const int g = lane >> 2, t = lane & 3;
    const int wm = (wid & 1) * 64, wn = (wid >> 1) * 32;
    const size_t bm0 = (size_t)blockIdx.y * 128;
    const size_t bn0 = (size_t)blockIdx.x * 128;

    const uint32_t aAs = smem_u32(As);
    const uint32_t aBs = smem_u32(Bs);
    const int offA = (lane & 15)*SA + (lane >> 4)*8;
    const int offB = ((lane & 7) + (lane >> 4)*8)*SA + ((lane >> 3) & 1)*8;

    float acc[4][4][4];
    #pragma unroll
    for (int a=0;a<4;a++)
        #pragma unroll
        for (int b=0;b<4;b++)
            #pragma unroll
            for (int c=0;c<4;c++) acc[a][b][c] = 0.0f;

    const int lr = tid >> 2;
    const int lc = (tid & 3) << 3;
    uint4 pa[2], pb[2];
    #pragma unroll
    for (int i=0;i<2;i++){
        int r = lr + i*64;
        pa[i] = *(const uint4*)&A [(bm0 + r)*K + lc];
        pb[i] = *(const uint4*)&Bt[(bn0 + r)*K + lc];
    }

    for (int k0 = 0; k0 < K; k0 += 32){
        __syncthreads();
        #pragma unroll
        for (int i=0;i<2;i++){
            int r = lr + i*64;
            *(uint4*)&As[r*SA + lc] = pa[i];
            *(uint4*)&Bs[r*SA + lc] = pb[i];
        }
        __syncthreads();
        if (k0 + 32 < K){
            #pragma unroll
            for (int i=0;i<2;i++){
                int r = lr + i*64;
                pa[i] = *(const uint4*)&A [(bm0 + r)*K + k0+32 + lc];
                pb[i] = *(const uint4*)&Bt[(bn0 + r)*K + k0+32 + lc];
            }
        }
        #pragma unroll
        for (int ks = 0; ks < 32; ks += 16){
            uint32_t af[4][4];
            #pragma unroll
            for (int mt=0; mt<4; mt++){
                uint32_t adr = aAs + 2*((wm + mt*16)*SA + ks + offA);
                LDSM4(af[mt][0], af[mt][1], af[mt][2], af[mt][3], adr);
            }
            uint32_t bh[2][4];
            #pragma unroll
            for (int np=0; np<2; np++){
                uint32_t adr = aBs + 2*((wn + np*16)*SA + ks + offB);
                LDSM4(bh[np][0], bh[np][1], bh[np][2], bh[np][3], adr);
            }
            #pragma unroll
            for (int np=0; np<2; np++){
                #pragma unroll
                for (int hf=0; hf<2; hf++){
                    int nt = np*2 + hf;
                    uint32_t b0 = bh[np][2*hf], b1 = bh[np][2*hf+1];
                    #pragma unroll
                    for (int mt=0; mt<4; mt++)
                        mma16816h(acc[mt][nt], af[mt], b0, b1);
                }
            }
        }
    }

    #pragma unroll
    for (int mt=0; mt<4; mt++){
        #pragma unroll
        for (int nt=0; nt<4; nt++){
            size_t n = bn0 + wn + nt*8 + 2*t;
            float b0v = bias[n], b1v = bias[n+1];
            size_t m = bm0 + wm + mt*16 + g;
            float v00 = acc[mt][nt][0] + b0v, v01 = acc[mt][nt][1] + b1v;
            float v10 = acc[mt][nt][2] + b0v, v11 = acc[mt][nt][3] + b1v;
            if (F16_OUT){
                *(uint32_t*)&Ch[m*N + n]     = pack2f16(v00, v01);
                *(uint32_t*)&Ch[(m+8)*N + n] = pack2f16(v10, v11);
            } else {
                float2 fa; fa.x = v00; fa.y = v01;
                float2 fb; fb.x = v10; fb.y = v11;
                *(float2*)&Cf[m*N + n]     = fa;
                *(float2*)&Cf[(m+8)*N + n] = fb;
            }
        }
    }
}

__global__ __launch_bounds__(256) void gemm_qkv_kernel(){
    gemm_core<true>(g_x16, g_Wt, g_bqkv, DMODEL, NQ, g_qh, nullptr);
}
__global__ __launch_bounds__(256) void gemm_out_kernel(const float* __restrict__ bp,
                                                       float* __restrict__ out){
    gemm_core<false>(g_ch, g_Wpt, bp, DMODEL, DMODEL, nullptr, out);
}

// ============================================================================
// Flash attention, fp16 1-term: S = Qh*Kh ; O += Ph*Vh.
// 128-q-row blocks, ldmatrix frags, cp.async double-buffered K/V.
// Q pre-scaled by QFOLD -> softmax = exp2(s - m).
// ============================================================================
#define KV_ARR   (64*72)
#define KV_ARRB  (KV_ARR*2)
#define KV_BUFB  (2*KV_ARRB)                 // Kh, Vh
#define ATTN_SMEM (128*72*2 + 2*KV_BUFB)     // 55296

__global__ __launch_bounds__(128, 3) void attn_mma(){
    extern __shared__ __align__(16) char smraw[];
    f16* Qh = (f16*)smraw;                 // [128][72] fp16
    const uint32_t aQh = smem_u32(Qh);
    const uint32_t aKV = aQh + 2*128*72;

    const int tid  = threadIdx.x;
    const int lane = tid & 31, wid = tid >> 5;
    const int g = lane >> 2, t = lane & 3;
    const int b = blockIdx.y / NHEAD, h = blockIdx.y % NHEAD;
    const int q0 = blockIdx.x * 128;
    const size_t rowbase = (size_t)b*SEQ*NQ + (size_t)h*HD;

    #pragma unroll
    for (int i=0;i<8;i++){
        int v = tid + i*128;
        int r = v >> 3, c = (v & 7) << 3;
        *(uint4*)&Qh[r*72 + c] = *(const uint4*)&g_qh[rowbase + (size_t)(q0+r)*NQ + c];
    }

    auto issue_kv = [&](int it, int bufIdx){
        uint32_t base = aKV + bufIdx*KV_BUFB;
        #pragma unroll
        for (int i=0;i<4;i++){
            int v = tid + i*128;
            int r = v >> 3, c = (v & 7) << 3;
            size_t grow = rowbase + (size_t)(it*64 + r)*NQ;
            uint32_t doff = 2*(r*72 + c);
            cp16(base + 0*KV_ARRB + doff, &g_qh[grow +   DMODEL + c]);   // Kh
            cp16(base + 1*KV_ARRB + doff, &g_qh[grow + 2*DMODEL + c]);   // Vh
        }
        CP_COMMIT();
    };

    const int offA = (lane & 15)*72 + (lane >> 4)*8;
    const int offB = ((lane & 7) + (lane >> 4)*8)*72 + ((lane >> 3) & 1)*8;
    const int offV = ((lane & 7) + ((lane >> 3) & 1)*8)*72 + (lane >> 4)*8;

    float m[2][2], l[2][2], o[2][8][4];
    #pragma unroll
    for (int mt=0;mt<2;mt++){
        m[mt][0]=-1e30f; m[mt][1]=-1e30f; l[mt][0]=0.0f; l[mt][1]=0.0f;
        #pragma unroll
        for (int e=0;e<8;e++){ o[mt][e][0]=0; o[mt][e][1]=0; o[mt][e][2]=0; o[mt][e][3]=0; }
    }
    const int NT = SEQ/64;

    issue_kv(0, 0);

    for (int it = 0; it < NT; it++){
        const int buf = it & 1;
        __syncthreads();
        if (it + 1 < NT){ issue_kv(it + 1, buf ^ 1); CP_WAIT(1); }
        else            { CP_WAIT(0); }
        __syncthreads();

        const uint32_t aKh = aKV + buf*KV_BUFB;
        const uint32_t aVh = aKh + KV_ARRB;

        // ---- S = Q K^T (fp16 1-term), 2 m-tiles per warp ----
        float s[2][8][4];
        #pragma unroll
        for (int mt=0;mt<2;mt++)
            #pragma unroll
            for (int nt=0;nt<8;nt++){ s[mt][nt][0]=0; s[mt][nt][1]=0; s[mt][nt][2]=0; s[mt][nt][3]=0; }

        #pragma unroll
        for (int ks=0; ks<64; ks+=16){
            uint32_t ah[2][4];
            #pragma unroll
            for (int mt=0; mt<2; mt++){
                uint32_t adr = aQh + 2*((wid*32 + mt*16)*72 + ks + offA);
                LDSM4(ah[mt][0], ah[mt][1], ah[mt][2], ah[mt][3], adr);
            }
            #pragma unroll
            for (int np=0; np<4; np++){
                uint32_t kh0,kh1,kh2,kh3;
                uint32_t adr = aKh + 2*((np*16)*72 + ks + offB);
                LDSM4(kh0,kh1,kh2,kh3, adr);
                #pragma unroll
                for (int mt=0; mt<2; mt++){
                    mma16816h(s[mt][2*np  ], ah[mt], kh0, kh1);
                    mma16816h(s[mt][2*np+1], ah[mt], kh2, kh3);
                }
            }
        }

        // ---- Online softmax per m-tile (base-2 domain, scores pre-scaled) ----
        uint32_t ph01[2][8], ph23[2][8];
        #pragma unroll
        for (int mt=0; mt<2; mt++){
            float rm0 = -1e30f, rm1 = -1e30f;
            #pragma unroll
            for (int nt=0;nt<8;nt++){
                rm0 = fmaxf(rm0, fmaxf(s[mt][nt][0], s[mt][nt][1]));
                rm1 = fmaxf(rm1, fmaxf(s[mt][nt][2], s[mt][nt][3]));
            }
            rm0 = fmaxf(rm0, __shfl_xor_sync(0xffffffffu, rm0, 1));
            rm0 = fmaxf(rm0, __shfl_xor_sync(0xffffffffu, rm0, 2));
            rm1 = fmaxf(rm1, __shfl_xor_sync(0xffffffffu, rm1, 1));
            rm1 = fmaxf(rm1, __shfl_xor_sync(0xffffffffu, rm1, 2));
            float mn0 = fmaxf(m[mt][0], rm0), mn1 = fmaxf(m[mt][1], rm1);
            float cr0 = exp2f(m[mt][0] - mn0), cr1 = exp2f(m[mt][1] - mn1);
            m[mt][0] = mn0; m[mt][1] = mn1;

            float rs0 = 0.0f, rs1 = 0.0f;
            #pragma unroll
            for (int nt=0;nt<8;nt++){
                float p0 = exp2f(s[mt][nt][0]-mn0), p1 = exp2f(s[mt][nt][1]-mn0);
                float p2 = exp2f(s[mt][nt][2]-mn1), p3 = exp2f(s[mt][nt][3]-mn1);
                rs0 += p0+p1; rs1 += p2+p3;
                ph01[mt][nt] = pack2f16(p0, p1);
                ph23[mt][nt] = pack2f16(p2, p3);
            }
            rs0 += __shfl_xor_sync(0xffffffffu, rs0, 1);
            rs0 += __shfl_xor_sync(0xffffffffu, rs0, 2);
            rs1 += __shfl_xor_sync(0xffffffffu, rs1, 1);
            rs1 += __shfl_xor_sync(0xffffffffu, rs1, 2);
            l[mt][0] = l[mt][0]*cr0 + rs0; l[mt][1] = l[mt][1]*cr1 + rs1;
            #pragma unroll
            for (int e=0;e<8;e++){
                o[mt][e][0]*=cr0; o[mt][e][1]*=cr0; o[mt][e][2]*=cr1; o[mt][e][3]*=cr1;
            }
        }

        // ---- O += P @ V (fp16 1-term) ----
        #pragma unroll
        for (int j2=0; j2<4; j2++){
            uint32_t aP[2][4];
            #pragma unroll
            for (int mt=0; mt<2; mt++){
                aP[mt][0]=ph01[mt][2*j2];   aP[mt][1]=ph23[mt][2*j2];
                aP[mt][2]=ph01[mt][2*j2+1]; aP[mt][3]=ph23[mt][2*j2+1];
            }
            #pragma unroll
            for (int ep=0; ep<4; ep++){
                uint32_t vh0,vh1,vh2,vh3;
                uint32_t adr = aVh + 2*((j2*16)*72 + ep*16 + offV);
                LDSM4T(vh0,vh1,vh2,vh3, adr);
                #pragma unroll
                for (int mt=0; mt<2; mt++){
                    mma16816h(o[mt][2*ep  ], aP[mt], vh0, vh1);
                    mma16816h(o[mt][2*ep+1], aP[mt], vh2, vh3);
                }
            }
        }
    }

    // ---- Normalize, write ctx fp16 ----
    #pragma unroll
    for (int mt=0; mt<2; mt++){
        float i0 = 1.0f/l[mt][0], i1 = 1.0f/l[mt][1];
        size_t row = (size_t)b*SEQ + q0 + wid*32 + mt*16 + g;
        #pragma unroll
        for (int et=0; et<8; et++){
            int n = h*HD + et*8 + 2*t;
            *(uint32_t*)&g_ch[row*DMODEL + n]     = pack2f16(o[mt][et][0]*i0, o[mt][et][1]*i0);
            *(uint32_t*)&g_ch[(row+8)*DMODEL + n] = pack2f16(o[mt][et][2]*i1, o[mt][et][3]*i1);
        }
    }
}

// ============================================================================
extern "C" void kernel_launch(void* const* d_in, const int* in_sizes, int n_in,
                              void* d_out, int out_size)
{
    const float* x  = (const float*)d_in[0];
    const float* Wq = (const float*)d_in[1];
    const float* bq = (const float*)d_in[2];
    const float* Wk = (const float*)d_in[3];
    const float* bk = (const float*)d_in[4];
    const float* Wv = (const float*)d_in[5];
    const float* bv = (const float*)d_in[6];
    const float* Wp = (const float*)d_in[7];
    const float* bp = (const float*)d_in[8];
    float* out = (float*)d_out;

    cvt_x_kernel<<<((size_t)MR*DMODEL + 255)/256, 256>>>(x);
    prep_all_kernel<<<(NQ*DMODEL + 255)/256, 256>>>(Wq, Wk, Wv, bq, bk, bv, Wp);
    gemm_qkv_kernel<<<dim3(NQ/128, MR/128), 256>>>();

    cudaFuncSetAttribute(attn_mma, cudaFuncAttributeMaxDynamicSharedMemorySize, ATTN_SMEM);
    attn_mma<<<dim3(SEQ/128, BBATCH*NHEAD), 128, ATTN_SMEM>>>();

    gemm_out_kernel<<<dim3(DMODEL/128, MR/128), 256>>>(bp, out);
}